// round 14
// baseline (speedup 1.0000x reference)
#include <cuda_runtime.h>
#include <cuda_fp16.h>
#include <math.h>

#define D_MODEL 768
#define N_HEADS 12
#define HEAD_DIM 64
#define N_LAYERS 12
#define SEQ 1024
#define BATCH 4
#define ROWS (BATCH * SEQ)       // 4096
#define D_FF (4 * D_MODEL)       // 3072
#define VOCAB 50257
#define VOCAB_P 50432            // padded to multiple of 256
#define WSZ (D_MODEL * D_MODEL)  // 589824

// fp16 GEMM smem: Asf 2*8*2*32*4 = 4096 words, Bs 2*16*264 = 8448 words
#define ASF_WORDS (2 * 8 * 2 * 32 * 4)
#define BS_WORDS  (2 * 16 * 264)
#define GEMM_SMEM ((ASF_WORDS + BS_WORDS) * 4)   // 50176 bytes

// ---------------- scratch (device globals; no allocation allowed) ----------------
__device__ float    g_h[ROWS * D_MODEL];
__device__ __half   g_a[ROWS * D_MODEL];     // fp16 activations (LN out)
__device__ unsigned g_q[ROWS * D_MODEL];     // tf32 q (attention)
__device__ unsigned g_k[ROWS * D_MODEL];
__device__ unsigned g_v[ROWS * D_MODEL];
__device__ __half   g_o[ROWS * D_MODEL];     // fp16 attn out
__device__ __half   g_m[ROWS * D_FF];        // fp16 FF1 out
__device__ float    g_part[3 * ROWS * D_MODEL];  // split-K partials
// fp16 pre-packed weights (half2 along K: word[k2][n] = (W[2k2][n], W[2k2+1][n]))
__device__ unsigned g_wq[N_LAYERS * WSZ / 2];
__device__ unsigned g_wk[N_LAYERS * WSZ / 2];
__device__ unsigned g_wv[N_LAYERS * WSZ / 2];
__device__ unsigned g_wp[N_LAYERS * WSZ / 2];
__device__ unsigned g_w1[N_LAYERS * WSZ * 2];
__device__ unsigned g_w2[N_LAYERS * WSZ * 2];
__device__ unsigned g_whp[(D_MODEL / 2) * VOCAB_P];

// ---------------- helpers ----------------
__device__ __forceinline__ unsigned f2tf(float x) {
    unsigned r;
    asm("cvt.rna.tf32.f32 %0, %1;" : "=r"(r) : "f"(x));
    return r;
}

__device__ __forceinline__ unsigned packh2(float lo, float hi) {
    __half2 t = __floats2half2_rn(lo, hi);
    return *reinterpret_cast<unsigned*>(&t);
}

__device__ __forceinline__ void mma_tf32(float* c, const unsigned* a, const unsigned* b) {
    asm volatile(
        "mma.sync.aligned.m16n8k8.row.col.f32.tf32.tf32.f32 "
        "{%0,%1,%2,%3}, {%4,%5,%6,%7}, {%8,%9}, {%0,%1,%2,%3};"
        : "+f"(c[0]), "+f"(c[1]), "+f"(c[2]), "+f"(c[3])
        : "r"(a[0]), "r"(a[1]), "r"(a[2]), "r"(a[3]), "r"(b[0]), "r"(b[1]));
}

__device__ __forceinline__ void mma_f16(float* c, const unsigned* a, const unsigned* b) {
    asm volatile(
        "mma.sync.aligned.m16n8k16.row.col.f32.f16.f16.f32 "
        "{%0,%1,%2,%3}, {%4,%5,%6,%7}, {%8,%9}, {%0,%1,%2,%3};"
        : "+f"(c[0]), "+f"(c[1]), "+f"(c[2]), "+f"(c[3])
        : "r"(a[0]), "r"(a[1]), "r"(a[2]), "r"(a[3]), "r"(b[0]), "r"(b[1]));
}

__device__ __forceinline__ void cp16(unsigned saddr, const unsigned* gptr) {
    asm volatile("cp.async.cg.shared.global [%0], [%1], 16;"
                 :: "r"(saddr), "l"(gptr) : "memory");
}

// ---------------- weight packing: fp32 [rows][N] -> half2 words [rows/2][N] ----------------
__global__ void pack_kernel(const float* __restrict__ src, unsigned* __restrict__ dst,
                            int rows2, int n4) {
    int i = blockIdx.x * 256 + threadIdx.x;
    if (i < rows2 * n4) {
        int r2 = i / n4, c = i % n4;
        size_t N = (size_t)n4 * 4;
        float4 a = *(const float4*)(src + (size_t)(2 * r2) * N + c * 4);
        float4 b = *(const float4*)(src + (size_t)(2 * r2 + 1) * N + c * 4);
        uint4 u;
        u.x = packh2(a.x, b.x); u.y = packh2(a.y, b.y);
        u.z = packh2(a.z, b.z); u.w = packh2(a.w, b.w);
        ((uint4*)dst)[i] = u;
    }
}

// headed qkv weights: [B=L*H][K][64] -> [B][K/2][64] half2 words
__global__ void pack_headed_kernel(const float* __restrict__ src, unsigned* __restrict__ dst,
                                   int nblocks, int K) {
    int i = blockIdx.x * 256 + threadIdx.x;
    int per = (K / 2) * 16;
    if (i < nblocks * per) {
        int b = i / per, rem = i % per;
        int r2 = rem / 16, c = rem % 16;
        const float* s0 = src + ((size_t)b * K + 2 * r2) * 64 + c * 4;
        float4 a = *(const float4*)(s0);
        float4 bb = *(const float4*)(s0 + 64);
        uint4 u;
        u.x = packh2(a.x, bb.x); u.y = packh2(a.y, bb.y);
        u.z = packh2(a.z, bb.z); u.w = packh2(a.w, bb.w);
        ((uint4*)dst)[i] = u;
    }
}

// LM head: [K][VOCAB] -> [K/2][VOCAB_P] half2 words, zero-padded
__global__ void pad_wh_kernel(const float* __restrict__ Wh, unsigned* __restrict__ WhP) {
    int r2 = blockIdx.y;
    int col = blockIdx.x * 256 + threadIdx.x;
    if (col < VOCAB_P) {
        float lo = 0.f, hi = 0.f;
        if (col < VOCAB) {
            lo = Wh[(size_t)(2 * r2) * VOCAB + col];
            hi = Wh[(size_t)(2 * r2 + 1) * VOCAB + col];
        }
        WhP[(size_t)r2 * VOCAB_P + col] = packh2(lo, hi);
    }
}

// ---------------- embedding ----------------
__global__ void embed_kernel(const int* __restrict__ x, const float* __restrict__ wte,
                             const float* __restrict__ wpe, float* __restrict__ h) {
    int row = blockIdx.x;
    int tok = x[row];
    int s = row & (SEQ - 1);
    const float* te = wte + (size_t)tok * D_MODEL;
    const float* pe = wpe + (size_t)s * D_MODEL;
    float* out = h + (size_t)row * D_MODEL;
    for (int d = threadIdx.x; d < D_MODEL; d += 256)
        out[d] = te[d] + pe[d];
}

// ---------------- LN core ----------------
template <bool DOUBLE>
__device__ __forceinline__
void ln_core(float v0, float v1, float v2,
             const float* __restrict__ w1, const float* __restrict__ b1,
             const float* __restrict__ w2, const float* __restrict__ b2,
             __half* __restrict__ yr, float* red, int tid) {
    red[tid] = v0 + v1 + v2;
    __syncthreads();
    for (int s = 128; s > 0; s >>= 1) { if (tid < s) red[tid] += red[tid + s]; __syncthreads(); }
    float mean = red[0] * (1.0f / D_MODEL);
    __syncthreads();
    float d0 = v0 - mean, d1 = v1 - mean, d2 = v2 - mean;
    red[tid] = d0 * d0 + d1 * d1 + d2 * d2;
    __syncthreads();
    for (int s = 128; s > 0; s >>= 1) { if (tid < s) red[tid] += red[tid + s]; __syncthreads(); }
    float rstd = rsqrtf(red[0] * (1.0f / D_MODEL) + 1e-5f);
    float y0 = d0 * rstd * w1[tid]       + b1[tid];
    float y1 = d1 * rstd * w1[tid + 256] + b1[tid + 256];
    float y2 = d2 * rstd * w1[tid + 512] + b1[tid + 512];

    if (DOUBLE) {
        __syncthreads();
        red[tid] = y0 + y1 + y2;
        __syncthreads();
        for (int s = 128; s > 0; s >>= 1) { if (tid < s) red[tid] += red[tid + s]; __syncthreads(); }
        float mean2 = red[0] * (1.0f / D_MODEL);
        __syncthreads();
        float e0 = y0 - mean2, e1 = y1 - mean2, e2 = y2 - mean2;
        red[tid] = e0 * e0 + e1 * e1 + e2 * e2;
        __syncthreads();
        for (int s = 128; s > 0; s >>= 1) { if (tid < s) red[tid] += red[tid + s]; __syncthreads(); }
        float rstd2 = rsqrtf(red[0] * (1.0f / D_MODEL) + 1e-5f);
        y0 = e0 * rstd2 * w2[tid]       + b2[tid];
        y1 = e1 * rstd2 * w2[tid + 256] + b2[tid + 256];
        y2 = e2 * rstd2 * w2[tid + 512] + b2[tid + 512];
    }
    yr[tid]       = __float2half_rn(y0);
    yr[tid + 256] = __float2half_rn(y1);
    yr[tid + 512] = __float2half_rn(y2);
}

template <bool DOUBLE>
__global__ void ln_kernel(const float* __restrict__ x,
                          const float* __restrict__ w1, const float* __restrict__ b1,
                          const float* __restrict__ w2, const float* __restrict__ b2,
                          __half* __restrict__ y) {
    __shared__ float red[256];
    int row = blockIdx.x, tid = threadIdx.x;
    const float* xr = x + (size_t)row * D_MODEL;
    ln_core<DOUBLE>(xr[tid], xr[tid + 256], xr[tid + 512],
                    w1, b1, w2, b2, y + (size_t)row * D_MODEL, red, tid);
}

// fused split-K reduce + residual + LN
template <bool DOUBLE>
__global__ void lnred_kernel(const float* __restrict__ part, const float* __restrict__ bias,
                             float* __restrict__ h,
                             const float* __restrict__ w1, const float* __restrict__ b1,
                             const float* __restrict__ w2, const float* __restrict__ b2,
                             __half* __restrict__ y) {
    __shared__ float red[256];
    int row = blockIdx.x, tid = threadIdx.x;
    float v[3];
#pragma unroll
    for (int i = 0; i < 3; i++) {
        int c = tid + i * 256;
        size_t idx = (size_t)row * D_MODEL + c;
        v[i] = part[idx] + part[idx + (size_t)ROWS * D_MODEL]
             + part[idx + 2 * (size_t)ROWS * D_MODEL] + bias[c] + h[idx];
        h[idx] = v[i];
    }
    ln_core<DOUBLE>(v[0], v[1], v[2], w1, b1, w2, b2,
                    y + (size_t)row * D_MODEL, red, tid);
}

// ---------------- FP16 tensor-core GEMM body (128x256 tile, BK=32) ----------------
// 8 warps, warp tile 64x64 (4 mi x 8 ni m16n8k16). A: fp16 [M][K] (read as half2 words).
// B: half2-packed words [K/2][N], or HEADED [H][K/2][64]. Output: fp32 / fp16 / tf32-bits.
template <bool GELU, bool RESID, bool HEADED, bool OUTTF, bool OUTH, bool PARTIAL>
__device__ __forceinline__
void gemm_body(const unsigned* __restrict__ A, const unsigned* __restrict__ B,
               const float* __restrict__ bias, const float* __restrict__ resid,
               void* __restrict__ Cv, int M, int N, int K, int NC,
               int bn, int bm, int kOff, int kLen) {
    extern __shared__ unsigned smu[];
    unsigned* Asf = smu;                  // [2][8 mi][2 ks][32][4]
    unsigned* Bsm = smu + ASF_WORDS;      // [2][16 k2][264]
    int tid = threadIdx.x;
    int lane = tid & 31, warp = tid >> 5;
    int wm = (warp & 1) * 64;
    int wn = (warp >> 1) * 64;
    int lr = lane >> 2;
    int lc = lane & 3;
    int lane_s = lr * 4 + (lc ^ ((lr >> 1) & 3));
    int K2 = K >> 1;

    float acc[4][8][4];
#pragma unroll
    for (int mi = 0; mi < 4; mi++)
#pragma unroll
        for (int ni = 0; ni < 8; ni++)
#pragma unroll
            for (int r = 0; r < 4; r++) acc[mi][ni][r] = 0.f;

    int arow_l = tid >> 1;
    int aks    = tid & 1;                  // ks half this thread stages
    int akw    = aks * 8;                  // word offset within BK/2=16 words
    int ami    = arow_l >> 4;
    int alr    = arow_l & 7;
    int ahi    = (arow_l >> 3) & 1;
    int asw    = (alr >> 1) & 3;
    int bkr    = tid >> 4;                 // 0..15 (k2 row)
    int bcl    = (tid & 15) * 4;           // word col within 64-chunk

    const unsigned* aptr = A + (size_t)(bm * 128 + arow_l) * K2 + (kOff >> 1) + akw;
    const unsigned* bptr[4];
    int strideB;
    if (HEADED) {
        strideB = 64;
#pragma unroll
        for (int c = 0; c < 4; c++)
            bptr[c] = B + ((size_t)(bn * 4 + c) * K2 + (kOff >> 1) + bkr) * 64 + bcl;
    } else {
        strideB = N;
#pragma unroll
        for (int c = 0; c < 4; c++)
            bptr[c] = B + (size_t)((kOff >> 1) + bkr) * N + bn * 256 + c * 64 + bcl;
    }
    unsigned bsbase = (unsigned)__cvta_generic_to_shared(Bsm) + (bkr * 264 + bcl) * 4;

    uint4 a0, a1;
    auto loadA = [&](int k0) {
        const unsigned* ap = aptr + (k0 >> 1);
        a0 = *(const uint4*)(ap);
        a1 = *(const uint4*)(ap + 4);
    };
    auto storeA = [&](int buf) {
        unsigned ar[8] = {a0.x, a0.y, a0.z, a0.w, a1.x, a1.y, a1.z, a1.w};
        unsigned* abase = Asf + (((buf * 8 + ami) * 2 + aks) * 32) * 4;
#pragma unroll
        for (int j = 0; j < 8; j++) {
            int ls   = alr * 4 + ((j & 3) ^ asw);
            int slot = ahi + 2 * (j >> 2);
            abase[ls * 4 + slot] = ar[j];
        }
    };
    auto stageB = [&](int k0, int buf) {
#pragma unroll
        for (int c = 0; c < 4; c++)
            cp16(bsbase + buf * 16 * 264 * 4 + c * 64 * 4,
                 bptr[c] + (size_t)(k0 >> 1) * strideB);
        asm volatile("cp.async.commit_group;" ::: "memory");
    };

    stageB(0, 0);
    loadA(0);
    storeA(0);
    asm volatile("cp.async.wait_all;" ::: "memory");
    __syncthreads();

    int cur = 0;
    for (int k0 = 0; k0 < kLen; k0 += 32) {
        bool has_next = (k0 + 32) < kLen;
        if (has_next) {
            stageB(k0 + 32, cur ^ 1);
            loadA(k0 + 32);
        }

#pragma unroll
        for (int ks = 0; ks < 2; ks++) {
            unsigned afr[4][4], bfr[8][2];
#pragma unroll
            for (int mi = 0; mi < 4; mi++) {
                int mig = (warp & 1) * 4 + mi;
                uint4 fa = *(const uint4*)(Asf + (((cur * 8 + mig) * 2 + ks) * 32 + lane_s) * 4);
                afr[mi][0] = fa.x; afr[mi][1] = fa.y;
                afr[mi][2] = fa.z; afr[mi][3] = fa.w;
            }
#pragma unroll
            for (int ni = 0; ni < 8; ni++) {
                int n0 = wn + ni * 8;
                bfr[ni][0] = Bsm[(cur * 16 + ks * 8 + lc) * 264 + n0 + lr];
                bfr[ni][1] = Bsm[(cur * 16 + ks * 8 + lc + 4) * 264 + n0 + lr];
            }
#pragma unroll
            for (int mi = 0; mi < 4; mi++)
#pragma unroll
                for (int ni = 0; ni < 8; ni++)
                    mma_f16(acc[mi][ni], afr[mi], bfr[ni]);
        }

        if (has_next) storeA(cur ^ 1);
        asm volatile("cp.async.wait_all;" ::: "memory");
        __syncthreads();
        cur ^= 1;
    }

    float*    Cf = (float*)Cv;
    unsigned* Cu = (unsigned*)Cv;
    __half*   Ch = (__half*)Cv;
#pragma unroll
    for (int mi = 0; mi < 4; mi++) {
        int row0 = bm * 128 + wm + mi * 16 + lr;
#pragma unroll
        for (int ni = 0; ni < 8; ni++) {
            int col = bn * 256 + wn + ni * 8 + lc * 2;
#pragma unroll
            for (int half = 0; half < 2; half++) {
                int row = row0 + half * 8;
                if (OUTH) {
                    float v0 = acc[mi][ni][half * 2 + 0] + bias[col];
                    float v1 = acc[mi][ni][half * 2 + 1] + bias[col + 1];
                    if (GELU) {
                        v0 = 0.5f * v0 * (1.0f + erff(v0 * 0.70710678118654752f));
                        v1 = 0.5f * v1 * (1.0f + erff(v1 * 0.70710678118654752f));
                    }
                    __half2 hv = __floats2half2_rn(v0, v1);
                    *(__half2*)(Ch + (size_t)row * NC + col) = hv;
                } else {
#pragma unroll
                    for (int cc = 0; cc < 2; cc++) {
                        int c = col + cc;
                        if (c < NC) {
                            float val = acc[mi][ni][half * 2 + cc];
                            if (PARTIAL) {
                                Cf[(size_t)row * NC + c] = val;
                            } else {
                                val += bias[c];
                                if (GELU) val = 0.5f * val * (1.0f + erff(val * 0.70710678118654752f));
                                if (RESID) val += resid[(size_t)row * NC + c];
                                if (OUTTF) Cu[(size_t)row * NC + c] = f2tf(val);
                                else       Cf[(size_t)row * NC + c] = val;
                            }
                        }
                    }
                }
            }
        }
    }
}

template <bool GELU, bool RESID, bool HEADED, bool OUTTF, bool OUTH, bool PARTIAL>
__global__ __launch_bounds__(256, 1)
void gemm_kernel(const unsigned* __restrict__ A, const unsigned* __restrict__ B,
                 const float* __restrict__ bias, const float* __restrict__ resid,
                 void* __restrict__ C, int M, int N, int K, int NC, int kLen) {
    void* Cv = C;
    int kOff = 0;
    if (PARTIAL) {
        kOff = blockIdx.z * kLen;
        Cv = (float*)C + (size_t)blockIdx.z * M * NC;
    }
    gemm_body<GELU, RESID, HEADED, OUTTF, OUTH, PARTIAL>(A, B, bias, resid, Cv, M, N, K, NC,
                                                         blockIdx.x, blockIdx.y, kOff, kLen);
}

// Fused Q/K/V projection: fp16 inputs, tf32-bit outputs for the attention kernel.
__global__ __launch_bounds__(256, 1)
void qkv_kernel(const unsigned* __restrict__ A,
                const unsigned* __restrict__ Wq, const unsigned* __restrict__ Wk,
                const unsigned* __restrict__ Wv,
                const float* __restrict__ bq, const float* __restrict__ bk,
                const float* __restrict__ bv,
                unsigned* __restrict__ q, unsigned* __restrict__ k, unsigned* __restrict__ v) {
    const unsigned* B  = (blockIdx.z == 0) ? Wq : (blockIdx.z == 1) ? Wk : Wv;
    const float* bias  = (blockIdx.z == 0) ? bq : (blockIdx.z == 1) ? bk : bv;
    unsigned*    C     = (blockIdx.z == 0) ? q  : (blockIdx.z == 1) ? k  : v;
    gemm_body<false, false, true, true, false, false>(A, B, bias, nullptr, C,
                                                      ROWS, D_MODEL, D_MODEL, D_MODEL,
                                                      blockIdx.x, blockIdx.y, 0, D_MODEL);
}

// ---------------- tensor-core causal attention (128-row Q tiles, tf32 mma) ----------------
#define QF_WORDS (8 * 8 * 32 * 4)            // 8192
#define KP_WORDS (64 * 36 * 2)               // 4608
#define VS_WORDS (64 * 68)                   // 4352
#define PS_WORDS (128 * 68)                  // 8704
#define ATT_SMEM ((QF_WORDS + KP_WORDS + VS_WORDS + PS_WORDS) * 4)
__global__ __launch_bounds__(256, 1)
void attn_kernel(const unsigned* __restrict__ q, const unsigned* __restrict__ k,
                 const unsigned* __restrict__ v, __half* __restrict__ o) {
    extern __shared__ unsigned smu[];
    unsigned* Qf = smu;
    unsigned* Kp = Qf + QF_WORDS;
    unsigned* Vs = Kp + KP_WORDS;
    unsigned* Ps = Vs + VS_WORDS;
    int qi = blockIdx.x, hh = blockIdx.y, b = blockIdx.z;
    int tid = threadIdx.x, lane = tid & 31, warp = tid >> 5;
    int lr = lane >> 2, lc = lane & 3;
    int lane_s = lr * 4 + (lc ^ ((lr >> 1) & 3));
    const size_t base = ((size_t)b * SEQ) * D_MODEL + (size_t)hh * HEAD_DIM;
    const float inv_scale = 0.03608439182435161f;   // 1/sqrt(768)

    // stage Q tile in fragment order
#pragma unroll
    for (int i = 0; i < 8; i++) {
        int id = tid + 256 * i;
        int r = id >> 4, ch = id & 15;
        uint4 qv = *(const uint4*)(q + base + (size_t)(qi * 128 + r) * D_MODEL + ch * 4);
        int wq = r >> 4, lrq = r & 15;
        int qlr = lrq & 7, qhi = lrq >> 3;
        int ks = ch >> 1, half = ch & 1;
        int slot = qhi + 2 * half;
        int qsw = (qlr >> 1) & 3;
        unsigned* qb = Qf + ((wq * 8 + ks) * 32) * 4;
        unsigned vals[4] = {qv.x, qv.y, qv.z, qv.w};
#pragma unroll
        for (int j = 0; j < 4; j++)
            qb[(qlr * 4 + (j ^ qsw)) * 4 + slot] = vals[j];
    }

    int str = tid >> 4, sch = tid & 15;
    int se4 = sch * 4;
    int sks = se4 >> 3, shalf = (se4 >> 2) & 1;
    uint4 kr[4], vr[4];
#pragma unroll
    for (int i = 0; i < 4; i++) {
        int r = str + 16 * i;
        size_t goff = base + (size_t)r * D_MODEL + se4;
        kr[i] = *(const uint4*)(k + goff);
        vr[i] = *(const uint4*)(v + goff);
    }

    float m_[2], l_[2], oacc[8][4];
    m_[0] = m_[1] = -1e30f; l_[0] = l_[1] = 0.f;
#pragma unroll
    for (int ni = 0; ni < 8; ni++)
#pragma unroll
        for (int r = 0; r < 4; r++) oacc[ni][r] = 0.f;

    unsigned* Prow0 = Ps + (warp * 16 + lr) * 68;
    unsigned* Prow1 = Prow0 + 8 * 68;

    int jmax = 2 * qi + 1;
    for (int j = 0; j <= jmax; j++) {
        __syncthreads();
#pragma unroll
        for (int i = 0; i < 4; i++) {
            int r = str + 16 * i;
            unsigned* kpb = Kp + (r * 36 + sks * 4) * 2 + shalf;
            kpb[0] = kr[i].x; kpb[2] = kr[i].y; kpb[4] = kr[i].z; kpb[6] = kr[i].w;
            *(uint4*)&Vs[r * 68 + se4] = vr[i];
        }
        if (j < jmax) {
#pragma unroll
            for (int i = 0; i < 4; i++) {
                int r = str + 16 * i;
                size_t goff = base + (size_t)((j + 1) * 64 + r) * D_MODEL + se4;
                kr[i] = *(const uint4*)(k + goff);
                vr[i] = *(const uint4*)(v + goff);
            }
        }
        __syncthreads();

        float s[8][4];
#pragma unroll
        for (int ni = 0; ni < 8; ni++)
#pragma unroll
            for (int r = 0; r < 4; r++) s[ni][r] = 0.f;

#pragma unroll
        for (int ks = 0; ks < 8; ks++) {
            unsigned a[4];
            uint4 fa = *(const uint4*)(Qf + ((warp * 8 + ks) * 32 + lane_s) * 4);
            a[0] = fa.x; a[1] = fa.y; a[2] = fa.z; a[3] = fa.w;
#pragma unroll
            for (int ni = 0; ni < 8; ni++) {
                uint2 kb = *(const uint2*)(Kp + ((ni * 8 + lr) * 36 + ks * 4 + lc) * 2);
                unsigned bfr[2] = {kb.x, kb.y};
                mma_tf32(s[ni], a, bfr);
            }
        }

#pragma unroll
        for (int half = 0; half < 2; half++) {
            int qr = qi * 128 + warp * 16 + lr + half * 8;
            float rm = -1e30f;
#pragma unroll
            for (int ni = 0; ni < 8; ni++)
#pragma unroll
                for (int cc = 0; cc < 2; cc++) {
                    float val = s[ni][half * 2 + cc] * inv_scale;
                    int col = j * 64 + ni * 8 + lc * 2 + cc;
                    if (col > qr) val = -1e30f;
                    s[ni][half * 2 + cc] = val;
                    rm = fmaxf(rm, val);
                }
            rm = fmaxf(rm, __shfl_xor_sync(0xffffffffu, rm, 1));
            rm = fmaxf(rm, __shfl_xor_sync(0xffffffffu, rm, 2));
            float mnew = fmaxf(m_[half], rm);
            float alpha = __expf(m_[half] - mnew);
            float psum = 0.f;
#pragma unroll
            for (int ni = 0; ni < 8; ni++)
#pragma unroll
                for (int cc = 0; cc < 2; cc++) {
                    float p = __expf(s[ni][half * 2 + cc] - mnew);
                    s[ni][half * 2 + cc] = p;
                    psum += p;
                }
            psum += __shfl_xor_sync(0xffffffffu, psum, 1);
            psum += __shfl_xor_sync(0xffffffffu, psum, 2);
            l_[half] = l_[half] * alpha + psum;
            m_[half] = mnew;
#pragma unroll
            for (int ni = 0; ni < 8; ni++) {
                oacc[ni][half * 2 + 0] *= alpha;
                oacc[ni][half * 2 + 1] *= alpha;
            }
        }

#pragma unroll
        for (int ni = 0; ni < 8; ni++) {
            Prow0[ni * 8 + lc * 2]     = f2tf(s[ni][0]);
            Prow0[ni * 8 + lc * 2 + 1] = f2tf(s[ni][1]);
            Prow1[ni * 8 + lc * 2]     = f2tf(s[ni][2]);
            Prow1[ni * 8 + lc * 2 + 1] = f2tf(s[ni][3]);
        }
        __syncwarp();

#pragma unroll
        for (int ks = 0; ks < 8; ks++) {
            int poff = ks * 8 + lc;
            unsigned a[4];
            a[0] = Prow0[poff];
            a[1] = Prow1[poff];
            a[2] = Prow0[poff + 4];
            a[3] = Prow1[poff + 4];
#pragma unroll
            for (int ni = 0; ni < 8; ni++) {
                unsigned bfr[2];
                bfr[0] = Vs[(ks * 8 + lc) * 68 + ni * 8 + lr];
                bfr[1] = Vs[(ks * 8 + lc + 4) * 68 + ni * 8 + lr];
                mma_tf32(oacc[ni], a, bfr);
            }
        }
    }

    float inv0 = 1.0f / l_[0], inv1 = 1.0f / l_[1];
    int row0 = qi * 128 + warp * 16 + lr;
#pragma unroll
    for (int ni = 0; ni < 8; ni++) {
        int col = ni * 8 + lc * 2;
        __half2* p0 = (__half2*)(o + base + (size_t)row0 * D_MODEL + col);
        __half2* p1 = (__half2*)(o + base + (size_t)(row0 + 8) * D_MODEL + col);
        *p0 = __floats2half2_rn(oacc[ni][0] * inv0, oacc[ni][1] * inv0);
        *p1 = __floats2half2_rn(oacc[ni][2] * inv1, oacc[ni][3] * inv1);
    }
}

// ---------------- launch ----------------
extern "C" void kernel_launch(void* const* d_in, const int* in_sizes, int n_in,
                              void* d_out, int out_size) {
    const int*   x      = (const int*)  d_in[0];
    const float* wte    = (const float*)d_in[1];
    const float* wpe    = (const float*)d_in[2];
    const float* ln1_w  = (const float*)d_in[3];
    const float* ln1_b  = (const float*)d_in[4];
    const float* Wq     = (const float*)d_in[5];
    const float* bq     = (const float*)d_in[6];
    const float* Wk     = (const float*)d_in[7];
    const float* bk     = (const float*)d_in[8];
    const float* Wv     = (const float*)d_in[9];
    const float* bv     = (const float*)d_in[10];
    const float* Wp     = (const float*)d_in[11];
    const float* bp     = (const float*)d_in[12];
    const float* ln2_w  = (const float*)d_in[13];
    const float* ln2_b  = (const float*)d_in[14];
    const float* lnfc_w = (const float*)d_in[15];
    const float* lnfc_b = (const float*)d_in[16];
    const float* W1     = (const float*)d_in[17];
    const float* b1     = (const float*)d_in[18];
    const float* W2     = (const float*)d_in[19];
    const float* b2     = (const float*)d_in[20];
    const float* lnf_w  = (const float*)d_in[21];
    const float* lnf_b  = (const float*)d_in[22];
    const float* Wh     = (const float*)d_in[23];
    const float* bh     = (const float*)d_in[24];
    float* out = (float*)d_out;

    float *h, *part;
    __half *a, *o, *m;
    unsigned *q, *k, *v, *whp, *wq, *wk, *wv, *wp, *w1, *w2;
    cudaGetSymbolAddress((void**)&h, g_h);
    cudaGetSymbolAddress((void**)&a, g_a);
    cudaGetSymbolAddress((void**)&q, g_q);
    cudaGetSymbolAddress((void**)&k, g_k);
    cudaGetSymbolAddress((void**)&v, g_v);
    cudaGetSymbolAddress((void**)&o, g_o);
    cudaGetSymbolAddress((void**)&m, g_m);
    cudaGetSymbolAddress((void**)&part, g_part);
    cudaGetSymbolAddress((void**)&whp, g_whp);
    cudaGetSymbolAddress((void**)&wq, g_wq);
    cudaGetSymbolAddress((void**)&wk, g_wk);
    cudaGetSymbolAddress((void**)&wv, g_wv);
    cudaGetSymbolAddress((void**)&wp, g_wp);
    cudaGetSymbolAddress((void**)&w1, g_w1);
    cudaGetSymbolAddress((void**)&w2, g_w2);

    cudaFuncSetAttribute(attn_kernel, cudaFuncAttributeMaxDynamicSharedMemorySize, ATT_SMEM);
    cudaFuncSetAttribute(qkv_kernel, cudaFuncAttributeMaxDynamicSharedMemorySize, GEMM_SMEM);
    cudaFuncSetAttribute(gemm_kernel<true, false, false, false, true, false>,
                         cudaFuncAttributeMaxDynamicSharedMemorySize, GEMM_SMEM);   // FF1
    cudaFuncSetAttribute(gemm_kernel<false, false, false, false, false, false>,
                         cudaFuncAttributeMaxDynamicSharedMemorySize, GEMM_SMEM);   // head
    cudaFuncSetAttribute(gemm_kernel<false, false, false, false, false, true>,
                         cudaFuncAttributeMaxDynamicSharedMemorySize, GEMM_SMEM);   // split-K

    // one-time weight packing (fp32 -> half2 along K)
    {
        int nH = N_LAYERS * N_HEADS * (D_MODEL / 2) * 16;     // headed qkv words/4
        pack_headed_kernel<<<(nH + 255) / 256, 256>>>(Wq, wq, N_LAYERS * N_HEADS, D_MODEL);
        pack_headed_kernel<<<(nH + 255) / 256, 256>>>(Wk, wk, N_LAYERS * N_HEADS, D_MODEL);
        pack_headed_kernel<<<(nH + 255) / 256, 256>>>(Wv, wv, N_LAYERS * N_HEADS, D_MODEL);
        int nP = (N_LAYERS * D_MODEL / 2) * (D_MODEL / 4);
        pack_kernel<<<(nP + 255) / 256, 256>>>(Wp, wp, N_LAYERS * D_MODEL / 2, D_MODEL / 4);
        int n1 = (N_LAYERS * D_MODEL / 2) * (D_FF / 4);
        pack_kernel<<<(n1 + 255) / 256, 256>>>(W1, w1, N_LAYERS * D_MODEL / 2, D_FF / 4);
        int n2 = (N_LAYERS * D_FF / 2) * (D_MODEL / 4);
        pack_kernel<<<(n2 + 255) / 256, 256>>>(W2, w2, N_LAYERS * D_FF / 2, D_MODEL / 4);
        pad_wh_kernel<<<dim3((VOCAB_P + 255) / 256, D_MODEL / 2), 256>>>(Wh, whp);
    }

    embed_kernel<<<ROWS, 256>>>(x, wte, wpe, h);

    dim3 gQKV(D_MODEL / 256, ROWS / 128, 3);          // (3, 32, 3)
    dim3 gSplit(D_MODEL / 256, ROWS / 128, 3);        // (3, 32, 3) split-K
    dim3 gFF1(D_FF / 256, ROWS / 128);                // (12, 32)
    dim3 gHead(VOCAB_P / 256, ROWS / 128);            // (197, 32)
    dim3 gAttn(SEQ / 128, N_HEADS, BATCH);            // (8, 12, 4)

    // layer 0 ln1
    ln_kernel<false><<<ROWS, 256>>>(h, ln1_w, ln1_b, nullptr, nullptr, a);

    const unsigned* aU = (const unsigned*)a;
    const unsigned* oU = (const unsigned*)o;
    const unsigned* mU = (const unsigned*)m;

    for (int l = 0; l < N_LAYERS; l++) {
        const unsigned* wq_l = wq + (size_t)l * WSZ / 2;
        const unsigned* wk_l = wk + (size_t)l * WSZ / 2;
        const unsigned* wv_l = wv + (size_t)l * WSZ / 2;
        const unsigned* wp_l = wp + (size_t)l * WSZ / 2;
        const unsigned* w1_l = w1 + (size_t)l * WSZ * 2;
        const unsigned* w2_l = w2 + (size_t)l * WSZ * 2;

        qkv_kernel<<<gQKV, 256, GEMM_SMEM>>>(aU, wq_l, wk_l, wv_l,
                                             bq + l * D_MODEL, bk + l * D_MODEL, bv + l * D_MODEL,
                                             q, k, v);

        attn_kernel<<<gAttn, 256, ATT_SMEM>>>(q, k, v, o);

        // proj: split-K x3 (K=768 -> 256 each), fused reduce + ln2∘lnfc
        gemm_kernel<false, false, false, false, false, true><<<gSplit, 256, GEMM_SMEM>>>(
            oU, wp_l, nullptr, nullptr, part, ROWS, D_MODEL, D_MODEL, D_MODEL, 256);
        lnred_kernel<true><<<ROWS, 256>>>(part, bp + l * D_MODEL, h,
                                          ln2_w + l * D_MODEL, ln2_b + l * D_MODEL,
                                          lnfc_w + l * D_MODEL, lnfc_b + l * D_MODEL, a);

        gemm_kernel<true, false, false, false, true, false><<<gFF1, 256, GEMM_SMEM>>>(
            aU, w1_l, b1 + l * D_FF, nullptr, m, ROWS, D_FF, D_MODEL, D_FF, D_MODEL);

        // FF2: split-K x3 (K=3072 -> 1024 each), fused reduce + next ln1 (or lnf)
        gemm_kernel<false, false, false, false, false, true><<<gSplit, 256, GEMM_SMEM>>>(
            mU, w2_l, nullptr, nullptr, part, ROWS, D_MODEL, D_FF, D_MODEL, 1024);
        if (l + 1 < N_LAYERS) {
            lnred_kernel<false><<<ROWS, 256>>>(part, b2 + l * D_MODEL, h,
                                               ln1_w + (l + 1) * D_MODEL,
                                               ln1_b + (l + 1) * D_MODEL,
                                               nullptr, nullptr, a);
        } else {
            lnred_kernel<false><<<ROWS, 256>>>(part, b2 + l * D_MODEL, h,
                                               lnf_w, lnf_b, nullptr, nullptr, a);
        }
    }

    gemm_kernel<false, false, false, false, false, false><<<gHead, 256, GEMM_SMEM>>>(
        aU, whp, bh, nullptr, out, ROWS, VOCAB_P, D_MODEL, VOCAB, D_MODEL);
}

// round 15
// speedup vs baseline: 1.0743x; 1.0743x over previous
#include <cuda_runtime.h>
#include <cuda_fp16.h>
#include <math.h>

#define D_MODEL 768
#define N_HEADS 12
#define HEAD_DIM 64
#define N_LAYERS 12
#define SEQ 1024
#define BATCH 4
#define ROWS (BATCH * SEQ)       // 4096
#define D_FF (4 * D_MODEL)       // 3072
#define VOCAB 50257
#define VOCAB_P 50432            // padded to multiple of 256
#define WSZ (D_MODEL * D_MODEL)  // 589824

// fp16 GEMM smem (BK=64): Asf 2*8*4*32*4 = 8192 words, Bs 2*32*264 = 16896 words
#define ASF_WORDS (2 * 8 * 4 * 32 * 4)
#define BS_WORDS  (2 * 32 * 264)
#define GEMM_SMEM ((ASF_WORDS + BS_WORDS) * 4)   // 100352 bytes

// ---------------- scratch (device globals; no allocation allowed) ----------------
__device__ float    g_h[ROWS * D_MODEL];
__device__ __half   g_a[ROWS * D_MODEL];     // fp16 activations (LN out)
__device__ unsigned g_q[ROWS * D_MODEL];     // tf32 q (attention)
__device__ unsigned g_k[ROWS * D_MODEL];
__device__ unsigned g_v[ROWS * D_MODEL];
__device__ __half   g_o[ROWS * D_MODEL];     // fp16 attn out
__device__ __half   g_m[ROWS * D_FF];        // fp16 FF1 out
__device__ float    g_part[3 * ROWS * D_MODEL];  // split-K partials
// fp16 pre-packed weights (half2 along K)
__device__ unsigned g_wq[N_LAYERS * WSZ / 2];
__device__ unsigned g_wk[N_LAYERS * WSZ / 2];
__device__ unsigned g_wv[N_LAYERS * WSZ / 2];
__device__ unsigned g_wp[N_LAYERS * WSZ / 2];
__device__ unsigned g_w1[N_LAYERS * WSZ * 2];
__device__ unsigned g_w2[N_LAYERS * WSZ * 2];
__device__ unsigned g_whp[(D_MODEL / 2) * VOCAB_P];

// ---------------- helpers ----------------
__device__ __forceinline__ unsigned f2tf(float x) {
    unsigned r;
    asm("cvt.rna.tf32.f32 %0, %1;" : "=r"(r) : "f"(x));
    return r;
}

__device__ __forceinline__ unsigned packh2(float lo, float hi) {
    __half2 t = __floats2half2_rn(lo, hi);
    return *reinterpret_cast<unsigned*>(&t);
}

__device__ __forceinline__ void mma_tf32(float* c, const unsigned* a, const unsigned* b) {
    asm volatile(
        "mma.sync.aligned.m16n8k8.row.col.f32.tf32.tf32.f32 "
        "{%0,%1,%2,%3}, {%4,%5,%6,%7}, {%8,%9}, {%0,%1,%2,%3};"
        : "+f"(c[0]), "+f"(c[1]), "+f"(c[2]), "+f"(c[3])
        : "r"(a[0]), "r"(a[1]), "r"(a[2]), "r"(a[3]), "r"(b[0]), "r"(b[1]));
}

__device__ __forceinline__ void mma_f16(float* c, const unsigned* a, const unsigned* b) {
    asm volatile(
        "mma.sync.aligned.m16n8k16.row.col.f32.f16.f16.f32 "
        "{%0,%1,%2,%3}, {%4,%5,%6,%7}, {%8,%9}, {%0,%1,%2,%3};"
        : "+f"(c[0]), "+f"(c[1]), "+f"(c[2]), "+f"(c[3])
        : "r"(a[0]), "r"(a[1]), "r"(a[2]), "r"(a[3]), "r"(b[0]), "r"(b[1]));
}

__device__ __forceinline__ void cp16(unsigned saddr, const unsigned* gptr) {
    asm volatile("cp.async.cg.shared.global [%0], [%1], 16;"
                 :: "r"(saddr), "l"(gptr) : "memory");
}

// ---------------- weight packing: fp32 [rows][N] -> half2 words [rows/2][N] ----------------
__global__ void pack_kernel(const float* __restrict__ src, unsigned* __restrict__ dst,
                            int rows2, int n4) {
    int i = blockIdx.x * 256 + threadIdx.x;
    if (i < rows2 * n4) {
        int r2 = i / n4, c = i % n4;
        size_t N = (size_t)n4 * 4;
        float4 a = *(const float4*)(src + (size_t)(2 * r2) * N + c * 4);
        float4 b = *(const float4*)(src + (size_t)(2 * r2 + 1) * N + c * 4);
        uint4 u;
        u.x = packh2(a.x, b.x); u.y = packh2(a.y, b.y);
        u.z = packh2(a.z, b.z); u.w = packh2(a.w, b.w);
        ((uint4*)dst)[i] = u;
    }
}

// headed qkv weights: [B=L*H][K][64] -> [B][K/2][64] half2 words
__global__ void pack_headed_kernel(const float* __restrict__ src, unsigned* __restrict__ dst,
                                   int nblocks, int K) {
    int i = blockIdx.x * 256 + threadIdx.x;
    int per = (K / 2) * 16;
    if (i < nblocks * per) {
        int b = i / per, rem = i % per;
        int r2 = rem / 16, c = rem % 16;
        const float* s0 = src + ((size_t)b * K + 2 * r2) * 64 + c * 4;
        float4 a = *(const float4*)(s0);
        float4 bb = *(const float4*)(s0 + 64);
        uint4 u;
        u.x = packh2(a.x, bb.x); u.y = packh2(a.y, bb.y);
        u.z = packh2(a.z, bb.z); u.w = packh2(a.w, bb.w);
        ((uint4*)dst)[i] = u;
    }
}

// LM head: [K][VOCAB] -> [K/2][VOCAB_P] half2 words, zero-padded
__global__ void pad_wh_kernel(const float* __restrict__ Wh, unsigned* __restrict__ WhP) {
    int r2 = blockIdx.y;
    int col = blockIdx.x * 256 + threadIdx.x;
    if (col < VOCAB_P) {
        float lo = 0.f, hi = 0.f;
        if (col < VOCAB) {
            lo = Wh[(size_t)(2 * r2) * VOCAB + col];
            hi = Wh[(size_t)(2 * r2 + 1) * VOCAB + col];
        }
        WhP[(size_t)r2 * VOCAB_P + col] = packh2(lo, hi);
    }
}

// ---------------- embedding ----------------
__global__ void embed_kernel(const int* __restrict__ x, const float* __restrict__ wte,
                             const float* __restrict__ wpe, float* __restrict__ h) {
    int row = blockIdx.x;
    int tok = x[row];
    int s = row & (SEQ - 1);
    const float* te = wte + (size_t)tok * D_MODEL;
    const float* pe = wpe + (size_t)s * D_MODEL;
    float* out = h + (size_t)row * D_MODEL;
    for (int d = threadIdx.x; d < D_MODEL; d += 256)
        out[d] = te[d] + pe[d];
}

// ---------------- LN core ----------------
template <bool DOUBLE>
__device__ __forceinline__
void ln_core(float v0, float v1, float v2,
             const float* __restrict__ w1, const float* __restrict__ b1,
             const float* __restrict__ w2, const float* __restrict__ b2,
             __half* __restrict__ yr, float* red, int tid) {
    red[tid] = v0 + v1 + v2;
    __syncthreads();
    for (int s = 128; s > 0; s >>= 1) { if (tid < s) red[tid] += red[tid + s]; __syncthreads(); }
    float mean = red[0] * (1.0f / D_MODEL);
    __syncthreads();
    float d0 = v0 - mean, d1 = v1 - mean, d2 = v2 - mean;
    red[tid] = d0 * d0 + d1 * d1 + d2 * d2;
    __syncthreads();
    for (int s = 128; s > 0; s >>= 1) { if (tid < s) red[tid] += red[tid + s]; __syncthreads(); }
    float rstd = rsqrtf(red[0] * (1.0f / D_MODEL) + 1e-5f);
    float y0 = d0 * rstd * w1[tid]       + b1[tid];
    float y1 = d1 * rstd * w1[tid + 256] + b1[tid + 256];
    float y2 = d2 * rstd * w1[tid + 512] + b1[tid + 512];

    if (DOUBLE) {
        __syncthreads();
        red[tid] = y0 + y1 + y2;
        __syncthreads();
        for (int s = 128; s > 0; s >>= 1) { if (tid < s) red[tid] += red[tid + s]; __syncthreads(); }
        float mean2 = red[0] * (1.0f / D_MODEL);
        __syncthreads();
        float e0 = y0 - mean2, e1 = y1 - mean2, e2 = y2 - mean2;
        red[tid] = e0 * e0 + e1 * e1 + e2 * e2;
        __syncthreads();
        for (int s = 128; s > 0; s >>= 1) { if (tid < s) red[tid] += red[tid + s]; __syncthreads(); }
        float rstd2 = rsqrtf(red[0] * (1.0f / D_MODEL) + 1e-5f);
        y0 = e0 * rstd2 * w2[tid]       + b2[tid];
        y1 = e1 * rstd2 * w2[tid + 256] + b2[tid + 256];
        y2 = e2 * rstd2 * w2[tid + 512] + b2[tid + 512];
    }
    yr[tid]       = __float2half_rn(y0);
    yr[tid + 256] = __float2half_rn(y1);
    yr[tid + 512] = __float2half_rn(y2);
}

template <bool DOUBLE>
__global__ void ln_kernel(const float* __restrict__ x,
                          const float* __restrict__ w1, const float* __restrict__ b1,
                          const float* __restrict__ w2, const float* __restrict__ b2,
                          __half* __restrict__ y) {
    __shared__ float red[256];
    int row = blockIdx.x, tid = threadIdx.x;
    const float* xr = x + (size_t)row * D_MODEL;
    ln_core<DOUBLE>(xr[tid], xr[tid + 256], xr[tid + 512],
                    w1, b1, w2, b2, y + (size_t)row * D_MODEL, red, tid);
}

// fused split-K reduce + residual + LN
template <bool DOUBLE>
__global__ void lnred_kernel(const float* __restrict__ part, const float* __restrict__ bias,
                             float* __restrict__ h,
                             const float* __restrict__ w1, const float* __restrict__ b1,
                             const float* __restrict__ w2, const float* __restrict__ b2,
                             __half* __restrict__ y) {
    __shared__ float red[256];
    int row = blockIdx.x, tid = threadIdx.x;
    float v[3];
#pragma unroll
    for (int i = 0; i < 3; i++) {
        int c = tid + i * 256;
        size_t idx = (size_t)row * D_MODEL + c;
        v[i] = part[idx] + part[idx + (size_t)ROWS * D_MODEL]
             + part[idx + 2 * (size_t)ROWS * D_MODEL] + bias[c] + h[idx];
        h[idx] = v[i];
    }
    ln_core<DOUBLE>(v[0], v[1], v[2], w1, b1, w2, b2,
                    y + (size_t)row * D_MODEL, red, tid);
}

// ---------------- FP16 tensor-core GEMM body (128x256 tile, BK=64) ----------------
// 8 warps, warp tile 64x64 (4 mi x 8 ni m16n8k16); double-buffered 64-deep k stages.
template <bool GELU, bool RESID, bool HEADED, bool OUTTF, bool OUTH, bool PARTIAL>
__device__ __forceinline__
void gemm_body(const unsigned* __restrict__ A, const unsigned* __restrict__ B,
               const float* __restrict__ bias, const float* __restrict__ resid,
               void* __restrict__ Cv, int M, int N, int K, int NC,
               int bn, int bm, int kOff, int kLen) {
    extern __shared__ unsigned smu[];
    unsigned* Asf = smu;                  // [2][8 mi][4 ks][32][4]
    unsigned* Bsm = smu + ASF_WORDS;      // [2][32 k2][264]
    int tid = threadIdx.x;
    int lane = tid & 31, warp = tid >> 5;
    int wm = (warp & 1) * 64;
    int wn = (warp >> 1) * 64;
    int lr = lane >> 2;
    int lc = lane & 3;
    int lane_s = lr * 4 + (lc ^ ((lr >> 1) & 3));
    int K2 = K >> 1;

    float acc[4][8][4];
#pragma unroll
    for (int mi = 0; mi < 4; mi++)
#pragma unroll
        for (int ni = 0; ni < 8; ni++)
#pragma unroll
            for (int r = 0; r < 4; r++) acc[mi][ni][r] = 0.f;

    int arow_l = tid >> 1;
    int akw    = (tid & 1) * 16;           // word offset within BK/2=32 words
    int aksb   = (tid & 1) * 2;            // base ks (stages ks pair)
    int ami    = arow_l >> 4;
    int alr    = arow_l & 7;
    int ahi    = (arow_l >> 3) & 1;
    int asw    = (alr >> 1) & 3;
    int bkr    = tid >> 4;                 // 0..15 (k2 row base)
    int bcl    = (tid & 15) * 4;           // word col within 64-chunk

    const unsigned* aptr = A + (size_t)(bm * 128 + arow_l) * K2 + (kOff >> 1) + akw;
    const unsigned* bptr[4];
    int strideB;
    if (HEADED) {
        strideB = 64;
#pragma unroll
        for (int c = 0; c < 4; c++)
            bptr[c] = B + ((size_t)(bn * 4 + c) * K2 + (kOff >> 1) + bkr) * 64 + bcl;
    } else {
        strideB = N;
#pragma unroll
        for (int c = 0; c < 4; c++)
            bptr[c] = B + (size_t)((kOff >> 1) + bkr) * N + bn * 256 + c * 64 + bcl;
    }
    unsigned bsbase = (unsigned)__cvta_generic_to_shared(Bsm) + (bkr * 264 + bcl) * 4;

    uint4 a0, a1, a2, a3;
    auto loadA = [&](int k0) {
        const unsigned* ap = aptr + (k0 >> 1);
        a0 = *(const uint4*)(ap);
        a1 = *(const uint4*)(ap + 4);
        a2 = *(const uint4*)(ap + 8);
        a3 = *(const uint4*)(ap + 12);
    };
    auto storeA = [&](int buf) {
        unsigned ar[16] = {a0.x, a0.y, a0.z, a0.w, a1.x, a1.y, a1.z, a1.w,
                           a2.x, a2.y, a2.z, a2.w, a3.x, a3.y, a3.z, a3.w};
#pragma unroll
        for (int half = 0; half < 2; half++) {
            int ks = aksb + half;
            unsigned* abase = Asf + (((buf * 8 + ami) * 4 + ks) * 32) * 4;
#pragma unroll
            for (int jj = 0; jj < 8; jj++) {
                int ls   = alr * 4 + ((jj & 3) ^ asw);
                int slot = ahi + 2 * (jj >> 2);
                abase[ls * 4 + slot] = ar[half * 8 + jj];
            }
        }
    };
    auto stageB = [&](int k0, int buf) {
#pragma unroll
        for (int rr = 0; rr < 2; rr++)
#pragma unroll
            for (int c = 0; c < 4; c++)
                cp16(bsbase + (buf * 32 + rr * 16) * 264 * 4 + c * 64 * 4,
                     bptr[c] + (size_t)((k0 >> 1) + rr * 16) * strideB);
        asm volatile("cp.async.commit_group;" ::: "memory");
    };

    stageB(0, 0);
    loadA(0);
    storeA(0);
    asm volatile("cp.async.wait_all;" ::: "memory");
    __syncthreads();

    int cur = 0;
    for (int k0 = 0; k0 < kLen; k0 += 64) {
        bool has_next = (k0 + 64) < kLen;
        if (has_next) {
            stageB(k0 + 64, cur ^ 1);
            loadA(k0 + 64);
        }

#pragma unroll
        for (int ks = 0; ks < 4; ks++) {
            unsigned afr[4][4], bfr[8][2];
#pragma unroll
            for (int mi = 0; mi < 4; mi++) {
                int mig = (warp & 1) * 4 + mi;
                uint4 fa = *(const uint4*)(Asf + (((cur * 8 + mig) * 4 + ks) * 32 + lane_s) * 4);
                afr[mi][0] = fa.x; afr[mi][1] = fa.y;
                afr[mi][2] = fa.z; afr[mi][3] = fa.w;
            }
#pragma unroll
            for (int ni = 0; ni < 8; ni++) {
                int n0 = wn + ni * 8;
                bfr[ni][0] = Bsm[(cur * 32 + ks * 8 + lc) * 264 + n0 + lr];
                bfr[ni][1] = Bsm[(cur * 32 + ks * 8 + lc + 4) * 264 + n0 + lr];
            }
#pragma unroll
            for (int mi = 0; mi < 4; mi++)
#pragma unroll
                for (int ni = 0; ni < 8; ni++)
                    mma_f16(acc[mi][ni], afr[mi], bfr[ni]);
        }

        if (has_next) storeA(cur ^ 1);
        asm volatile("cp.async.wait_all;" ::: "memory");
        __syncthreads();
        cur ^= 1;
    }

    float*    Cf = (float*)Cv;
    unsigned* Cu = (unsigned*)Cv;
    __half*   Ch = (__half*)Cv;
#pragma unroll
    for (int mi = 0; mi < 4; mi++) {
        int row0 = bm * 128 + wm + mi * 16 + lr;
#pragma unroll
        for (int ni = 0; ni < 8; ni++) {
            int col = bn * 256 + wn + ni * 8 + lc * 2;
#pragma unroll
            for (int half = 0; half < 2; half++) {
                int row = row0 + half * 8;
                if (OUTH) {
                    float v0 = acc[mi][ni][half * 2 + 0] + bias[col];
                    float v1 = acc[mi][ni][half * 2 + 1] + bias[col + 1];
                    if (GELU) {
                        v0 = 0.5f * v0 * (1.0f + erff(v0 * 0.70710678118654752f));
                        v1 = 0.5f * v1 * (1.0f + erff(v1 * 0.70710678118654752f));
                    }
                    __half2 hv = __floats2half2_rn(v0, v1);
                    *(__half2*)(Ch + (size_t)row * NC + col) = hv;
                } else {
#pragma unroll
                    for (int cc = 0; cc < 2; cc++) {
                        int c = col + cc;
                        if (c < NC) {
                            float val = acc[mi][ni][half * 2 + cc];
                            if (PARTIAL) {
                                Cf[(size_t)row * NC + c] = val;
                            } else {
                                val += bias[c];
                                if (GELU) val = 0.5f * val * (1.0f + erff(val * 0.70710678118654752f));
                                if (RESID) val += resid[(size_t)row * NC + c];
                                if (OUTTF) Cu[(size_t)row * NC + c] = f2tf(val);
                                else       Cf[(size_t)row * NC + c] = val;
                            }
                        }
                    }
                }
            }
        }
    }
}

template <bool GELU, bool RESID, bool HEADED, bool OUTTF, bool OUTH, bool PARTIAL>
__global__ __launch_bounds__(256, 1)
void gemm_kernel(const unsigned* __restrict__ A, const unsigned* __restrict__ B,
                 const float* __restrict__ bias, const float* __restrict__ resid,
                 void* __restrict__ C, int M, int N, int K, int NC, int kLen) {
    void* Cv = C;
    int kOff = 0;
    if (PARTIAL) {
        kOff = blockIdx.z * kLen;
        Cv = (float*)C + (size_t)blockIdx.z * M * NC;
    }
    gemm_body<GELU, RESID, HEADED, OUTTF, OUTH, PARTIAL>(A, B, bias, resid, Cv, M, N, K, NC,
                                                         blockIdx.x, blockIdx.y, kOff, kLen);
}

// Fused Q/K/V projection: fp16 inputs, tf32-bit outputs for the attention kernel.
__global__ __launch_bounds__(256, 1)
void qkv_kernel(const unsigned* __restrict__ A,
                const unsigned* __restrict__ Wq, const unsigned* __restrict__ Wk,
                const unsigned* __restrict__ Wv,
                const float* __restrict__ bq, const float* __restrict__ bk,
                const float* __restrict__ bv,
                unsigned* __restrict__ q, unsigned* __restrict__ k, unsigned* __restrict__ v) {
    const unsigned* B  = (blockIdx.z == 0) ? Wq : (blockIdx.z == 1) ? Wk : Wv;
    const float* bias  = (blockIdx.z == 0) ? bq : (blockIdx.z == 1) ? bk : bv;
    unsigned*    C     = (blockIdx.z == 0) ? q  : (blockIdx.z == 1) ? k  : v;
    gemm_body<false, false, true, true, false, false>(A, B, bias, nullptr, C,
                                                      ROWS, D_MODEL, D_MODEL, D_MODEL,
                                                      blockIdx.x, blockIdx.y, 0, D_MODEL);
}

// ---------------- tensor-core causal attention (128-row Q tiles, tf32 mma) ----------------
#define QF_WORDS (8 * 8 * 32 * 4)            // 8192
#define KP_WORDS (64 * 36 * 2)               // 4608
#define VS_WORDS (64 * 68)                   // 4352
#define PS_WORDS (128 * 68)                  // 8704
#define ATT_SMEM ((QF_WORDS + KP_WORDS + VS_WORDS + PS_WORDS) * 4)
__global__ __launch_bounds__(256, 1)
void attn_kernel(const unsigned* __restrict__ q, const unsigned* __restrict__ k,
                 const unsigned* __restrict__ v, __half* __restrict__ o) {
    extern __shared__ unsigned smu[];
    unsigned* Qf = smu;
    unsigned* Kp = Qf + QF_WORDS;
    unsigned* Vs = Kp + KP_WORDS;
    unsigned* Ps = Vs + VS_WORDS;
    int qi = blockIdx.x, hh = blockIdx.y, b = blockIdx.z;
    int tid = threadIdx.x, lane = tid & 31, warp = tid >> 5;
    int lr = lane >> 2, lc = lane & 3;
    int lane_s = lr * 4 + (lc ^ ((lr >> 1) & 3));
    const size_t base = ((size_t)b * SEQ) * D_MODEL + (size_t)hh * HEAD_DIM;
    const float inv_scale = 0.03608439182435161f;   // 1/sqrt(768)

#pragma unroll
    for (int i = 0; i < 8; i++) {
        int id = tid + 256 * i;
        int r = id >> 4, ch = id & 15;
        uint4 qv = *(const uint4*)(q + base + (size_t)(qi * 128 + r) * D_MODEL + ch * 4);
        int wq = r >> 4, lrq = r & 15;
        int qlr = lrq & 7, qhi = lrq >> 3;
        int ks = ch >> 1, half = ch & 1;
        int slot = qhi + 2 * half;
        int qsw = (qlr >> 1) & 3;
        unsigned* qb = Qf + ((wq * 8 + ks) * 32) * 4;
        unsigned vals[4] = {qv.x, qv.y, qv.z, qv.w};
#pragma unroll
        for (int j = 0; j < 4; j++)
            qb[(qlr * 4 + (j ^ qsw)) * 4 + slot] = vals[j];
    }

    int str = tid >> 4, sch = tid & 15;
    int se4 = sch * 4;
    int sks = se4 >> 3, shalf = (se4 >> 2) & 1;
    uint4 kr[4], vr[4];
#pragma unroll
    for (int i = 0; i < 4; i++) {
        int r = str + 16 * i;
        size_t goff = base + (size_t)r * D_MODEL + se4;
        kr[i] = *(const uint4*)(k + goff);
        vr[i] = *(const uint4*)(v + goff);
    }

    float m_[2], l_[2], oacc[8][4];
    m_[0] = m_[1] = -1e30f; l_[0] = l_[1] = 0.f;
#pragma unroll
    for (int ni = 0; ni < 8; ni++)
#pragma unroll
        for (int r = 0; r < 4; r++) oacc[ni][r] = 0.f;

    unsigned* Prow0 = Ps + (warp * 16 + lr) * 68;
    unsigned* Prow1 = Prow0 + 8 * 68;

    int jmax = 2 * qi + 1;
    for (int j = 0; j <= jmax; j++) {
        __syncthreads();
#pragma unroll
        for (int i = 0; i < 4; i++) {
            int r = str + 16 * i;
            unsigned* kpb = Kp + (r * 36 + sks * 4) * 2 + shalf;
            kpb[0] = kr[i].x; kpb[2] = kr[i].y; kpb[4] = kr[i].z; kpb[6] = kr[i].w;
            *(uint4*)&Vs[r * 68 + se4] = vr[i];
        }
        if (j < jmax) {
#pragma unroll
            for (int i = 0; i < 4; i++) {
                int r = str + 16 * i;
                size_t goff = base + (size_t)((j + 1) * 64 + r) * D_MODEL + se4;
                kr[i] = *(const uint4*)(k + goff);
                vr[i] = *(const uint4*)(v + goff);
            }
        }
        __syncthreads();

        float s[8][4];
#pragma unroll
        for (int ni = 0; ni < 8; ni++)
#pragma unroll
            for (int r = 0; r < 4; r++) s[ni][r] = 0.f;

#pragma unroll
        for (int ks = 0; ks < 8; ks++) {
            unsigned a[4];
            uint4 fa = *(const uint4*)(Qf + ((warp * 8 + ks) * 32 + lane_s) * 4);
            a[0] = fa.x; a[1] = fa.y; a[2] = fa.z; a[3] = fa.w;
#pragma unroll
            for (int ni = 0; ni < 8; ni++) {
                uint2 kb = *(const uint2*)(Kp + ((ni * 8 + lr) * 36 + ks * 4 + lc) * 2);
                unsigned bfr[2] = {kb.x, kb.y};
                mma_tf32(s[ni], a, bfr);
            }
        }

#pragma unroll
        for (int half = 0; half < 2; half++) {
            int qr = qi * 128 + warp * 16 + lr + half * 8;
            float rm = -1e30f;
#pragma unroll
            for (int ni = 0; ni < 8; ni++)
#pragma unroll
                for (int cc = 0; cc < 2; cc++) {
                    float val = s[ni][half * 2 + cc] * inv_scale;
                    int col = j * 64 + ni * 8 + lc * 2 + cc;
                    if (col > qr) val = -1e30f;
                    s[ni][half * 2 + cc] = val;
                    rm = fmaxf(rm, val);
                }
            rm = fmaxf(rm, __shfl_xor_sync(0xffffffffu, rm, 1));
            rm = fmaxf(rm, __shfl_xor_sync(0xffffffffu, rm, 2));
            float mnew = fmaxf(m_[half], rm);
            float alpha = __expf(m_[half] - mnew);
            float psum = 0.f;
#pragma unroll
            for (int ni = 0; ni < 8; ni++)
#pragma unroll
                for (int cc = 0; cc < 2; cc++) {
                    float p = __expf(s[ni][half * 2 + cc] - mnew);
                    s[ni][half * 2 + cc] = p;
                    psum += p;
                }
            psum += __shfl_xor_sync(0xffffffffu, psum, 1);
            psum += __shfl_xor_sync(0xffffffffu, psum, 2);
            l_[half] = l_[half] * alpha + psum;
            m_[half] = mnew;
#pragma unroll
            for (int ni = 0; ni < 8; ni++) {
                oacc[ni][half * 2 + 0] *= alpha;
                oacc[ni][half * 2 + 1] *= alpha;
            }
        }

#pragma unroll
        for (int ni = 0; ni < 8; ni++) {
            Prow0[ni * 8 + lc * 2]     = f2tf(s[ni][0]);
            Prow0[ni * 8 + lc * 2 + 1] = f2tf(s[ni][1]);
            Prow1[ni * 8 + lc * 2]     = f2tf(s[ni][2]);
            Prow1[ni * 8 + lc * 2 + 1] = f2tf(s[ni][3]);
        }
        __syncwarp();

#pragma unroll
        for (int ks = 0; ks < 8; ks++) {
            int poff = ks * 8 + lc;
            unsigned a[4];
            a[0] = Prow0[poff];
            a[1] = Prow1[poff];
            a[2] = Prow0[poff + 4];
            a[3] = Prow1[poff + 4];
#pragma unroll
            for (int ni = 0; ni < 8; ni++) {
                unsigned bfr[2];
                bfr[0] = Vs[(ks * 8 + lc) * 68 + ni * 8 + lr];
                bfr[1] = Vs[(ks * 8 + lc + 4) * 68 + ni * 8 + lr];
                mma_tf32(oacc[ni], a, bfr);
            }
        }
    }

    float inv0 = 1.0f / l_[0], inv1 = 1.0f / l_[1];
    int row0 = qi * 128 + warp * 16 + lr;
#pragma unroll
    for (int ni = 0; ni < 8; ni++) {
        int col = ni * 8 + lc * 2;
        __half2* p0 = (__half2*)(o + base + (size_t)row0 * D_MODEL + col);
        __half2* p1 = (__half2*)(o + base + (size_t)(row0 + 8) * D_MODEL + col);
        *p0 = __floats2half2_rn(oacc[ni][0] * inv0, oacc[ni][1] * inv0);
        *p1 = __floats2half2_rn(oacc[ni][2] * inv1, oacc[ni][3] * inv1);
    }
}

// ---------------- launch ----------------
extern "C" void kernel_launch(void* const* d_in, const int* in_sizes, int n_in,
                              void* d_out, int out_size) {
    const int*   x      = (const int*)  d_in[0];
    const float* wte    = (const float*)d_in[1];
    const float* wpe    = (const float*)d_in[2];
    const float* ln1_w  = (const float*)d_in[3];
    const float* ln1_b  = (const float*)d_in[4];
    const float* Wq     = (const float*)d_in[5];
    const float* bq     = (const float*)d_in[6];
    const float* Wk     = (const float*)d_in[7];
    const float* bk     = (const float*)d_in[8];
    const float* Wv     = (const float*)d_in[9];
    const float* bv     = (const float*)d_in[10];
    const float* Wp     = (const float*)d_in[11];
    const float* bp     = (const float*)d_in[12];
    const float* ln2_w  = (const float*)d_in[13];
    const float* ln2_b  = (const float*)d_in[14];
    const float* lnfc_w = (const float*)d_in[15];
    const float* lnfc_b = (const float*)d_in[16];
    const float* W1     = (const float*)d_in[17];
    const float* b1     = (const float*)d_in[18];
    const float* W2     = (const float*)d_in[19];
    const float* b2     = (const float*)d_in[20];
    const float* lnf_w  = (const float*)d_in[21];
    const float* lnf_b  = (const float*)d_in[22];
    const float* Wh     = (const float*)d_in[23];
    const float* bh     = (const float*)d_in[24];
    float* out = (float*)d_out;

    float *h, *part;
    __half *a, *o, *m;
    unsigned *q, *k, *v, *whp, *wq, *wk, *wv, *wp, *w1, *w2;
    cudaGetSymbolAddress((void**)&h, g_h);
    cudaGetSymbolAddress((void**)&a, g_a);
    cudaGetSymbolAddress((void**)&q, g_q);
    cudaGetSymbolAddress((void**)&k, g_k);
    cudaGetSymbolAddress((void**)&v, g_v);
    cudaGetSymbolAddress((void**)&o, g_o);
    cudaGetSymbolAddress((void**)&m, g_m);
    cudaGetSymbolAddress((void**)&part, g_part);
    cudaGetSymbolAddress((void**)&whp, g_whp);
    cudaGetSymbolAddress((void**)&wq, g_wq);
    cudaGetSymbolAddress((void**)&wk, g_wk);
    cudaGetSymbolAddress((void**)&wv, g_wv);
    cudaGetSymbolAddress((void**)&wp, g_wp);
    cudaGetSymbolAddress((void**)&w1, g_w1);
    cudaGetSymbolAddress((void**)&w2, g_w2);

    cudaFuncSetAttribute(attn_kernel, cudaFuncAttributeMaxDynamicSharedMemorySize, ATT_SMEM);
    cudaFuncSetAttribute(qkv_kernel, cudaFuncAttributeMaxDynamicSharedMemorySize, GEMM_SMEM);
    cudaFuncSetAttribute(gemm_kernel<true, false, false, false, true, false>,
                         cudaFuncAttributeMaxDynamicSharedMemorySize, GEMM_SMEM);   // FF1
    cudaFuncSetAttribute(gemm_kernel<false, false, false, false, false, false>,
                         cudaFuncAttributeMaxDynamicSharedMemorySize, GEMM_SMEM);   // head
    cudaFuncSetAttribute(gemm_kernel<false, false, false, false, false, true>,
                         cudaFuncAttributeMaxDynamicSharedMemorySize, GEMM_SMEM);   // split-K

    // one-time weight packing (fp32 -> half2 along K)
    {
        int nH = N_LAYERS * N_HEADS * (D_MODEL / 2) * 16;
        pack_headed_kernel<<<(nH + 255) / 256, 256>>>(Wq, wq, N_LAYERS * N_HEADS, D_MODEL);
        pack_headed_kernel<<<(nH + 255) / 256, 256>>>(Wk, wk, N_LAYERS * N_HEADS, D_MODEL);
        pack_headed_kernel<<<(nH + 255) / 256, 256>>>(Wv, wv, N_LAYERS * N_HEADS, D_MODEL);
        int nP = (N_LAYERS * D_MODEL / 2) * (D_MODEL / 4);
        pack_kernel<<<(nP + 255) / 256, 256>>>(Wp, wp, N_LAYERS * D_MODEL / 2, D_MODEL / 4);
        int n1 = (N_LAYERS * D_MODEL / 2) * (D_FF / 4);
        pack_kernel<<<(n1 + 255) / 256, 256>>>(W1, w1, N_LAYERS * D_MODEL / 2, D_FF / 4);
        int n2 = (N_LAYERS * D_FF / 2) * (D_MODEL / 4);
        pack_kernel<<<(n2 + 255) / 256, 256>>>(W2, w2, N_LAYERS * D_FF / 2, D_MODEL / 4);
        pad_wh_kernel<<<dim3((VOCAB_P + 255) / 256, D_MODEL / 2), 256>>>(Wh, whp);
    }

    embed_kernel<<<ROWS, 256>>>(x, wte, wpe, h);

    dim3 gQKV(D_MODEL / 256, ROWS / 128, 3);          // (3, 32, 3)
    dim3 gSplit(D_MODEL / 256, ROWS / 128, 3);        // (3, 32, 3) split-K
    dim3 gFF1(D_FF / 256, ROWS / 128);                // (12, 32)
    dim3 gHead(VOCAB_P / 256, ROWS / 128);            // (197, 32)
    dim3 gAttn(SEQ / 128, N_HEADS, BATCH);            // (8, 12, 4)

    // layer 0 ln1
    ln_kernel<false><<<ROWS, 256>>>(h, ln1_w, ln1_b, nullptr, nullptr, a);

    const unsigned* aU = (const unsigned*)a;
    const unsigned* oU = (const unsigned*)o;
    const unsigned* mU = (const unsigned*)m;

    for (int l = 0; l < N_LAYERS; l++) {
        const unsigned* wq_l = wq + (size_t)l * WSZ / 2;
        const unsigned* wk_l = wk + (size_t)l * WSZ / 2;
        const unsigned* wv_l = wv + (size_t)l * WSZ / 2;
        const unsigned* wp_l = wp + (size_t)l * WSZ / 2;
        const unsigned* w1_l = w1 + (size_t)l * WSZ * 2;
        const unsigned* w2_l = w2 + (size_t)l * WSZ * 2;

        qkv_kernel<<<gQKV, 256, GEMM_SMEM>>>(aU, wq_l, wk_l, wv_l,
                                             bq + l * D_MODEL, bk + l * D_MODEL, bv + l * D_MODEL,
                                             q, k, v);

        attn_kernel<<<gAttn, 256, ATT_SMEM>>>(q, k, v, o);

        // proj: split-K x3 (K=768 -> 256 each), fused reduce + ln2∘lnfc
        gemm_kernel<false, false, false, false, false, true><<<gSplit, 256, GEMM_SMEM>>>(
            oU, wp_l, nullptr, nullptr, part, ROWS, D_MODEL, D_MODEL, D_MODEL, 256);
        lnred_kernel<true><<<ROWS, 256>>>(part, bp + l * D_MODEL, h,
                                          ln2_w + l * D_MODEL, ln2_b + l * D_MODEL,
                                          lnfc_w + l * D_MODEL, lnfc_b + l * D_MODEL, a);

        gemm_kernel<true, false, false, false, true, false><<<gFF1, 256, GEMM_SMEM>>>(
            aU, w1_l, b1 + l * D_FF, nullptr, m, ROWS, D_FF, D_MODEL, D_FF, D_MODEL);

        // FF2: split-K x3 (K=3072 -> 1024 each), fused reduce + next ln1 (or lnf)
        gemm_kernel<false, false, false, false, false, true><<<gSplit, 256, GEMM_SMEM>>>(
            mU, w2_l, nullptr, nullptr, part, ROWS, D_MODEL, D_FF, D_MODEL, 1024);
        if (l + 1 < N_LAYERS) {
            lnred_kernel<false><<<ROWS, 256>>>(part, b2 + l * D_MODEL, h,
                                               ln1_w + (l + 1) * D_MODEL,
                                               ln1_b + (l + 1) * D_MODEL,
                                               nullptr, nullptr, a);
        } else {
            lnred_kernel<false><<<ROWS, 256>>>(part, b2 + l * D_MODEL, h,
                                               lnf_w, lnf_b, nullptr, nullptr, a);
        }
    }

    gemm_kernel<false, false, false, false, false, false><<<gHead, 256, GEMM_SMEM>>>(
        aU, whp, bh, nullptr, out, ROWS, VOCAB_P, D_MODEL, VOCAB, D_MODEL);
}

// round 16
// speedup vs baseline: 1.2279x; 1.1430x over previous
#include <cuda_runtime.h>
#include <cuda_fp16.h>
#include <math.h>

#define D_MODEL 768
#define N_HEADS 12
#define HEAD_DIM 64
#define N_LAYERS 12
#define SEQ 1024
#define BATCH 4
#define ROWS (BATCH * SEQ)       // 4096
#define D_FF (4 * D_MODEL)       // 3072
#define VOCAB 50257
#define VOCAB_P 50432            // padded to multiple of 256
#define WSZ (D_MODEL * D_MODEL)  // 589824

// fp16 GEMM smem (BK=64): Asf 2*8*4*32*4 = 8192 words, Bs 2*32*264 = 16896 words
#define ASF_WORDS (2 * 8 * 4 * 32 * 4)
#define BS_WORDS  (2 * 32 * 264)
#define GEMM_SMEM ((ASF_WORDS + BS_WORDS) * 4)   // 100352 bytes

// ---------------- scratch (device globals; no allocation allowed) ----------------
__device__ float    g_h[ROWS * D_MODEL];
__device__ __half   g_a[ROWS * D_MODEL];     // fp16 activations (LN out)
__device__ __half   g_q[ROWS * D_MODEL];     // fp16 q
__device__ __half   g_k[ROWS * D_MODEL];
__device__ __half   g_v[ROWS * D_MODEL];
__device__ __half   g_o[ROWS * D_MODEL];     // fp16 attn out
__device__ __half   g_m[ROWS * D_FF];        // fp16 FF1 out
__device__ float    g_part[3 * ROWS * D_MODEL];  // split-K partials
// fp16 pre-packed weights (half2 along K)
__device__ unsigned g_wq[N_LAYERS * WSZ / 2];
__device__ unsigned g_wk[N_LAYERS * WSZ / 2];
__device__ unsigned g_wv[N_LAYERS * WSZ / 2];
__device__ unsigned g_wp[N_LAYERS * WSZ / 2];
__device__ unsigned g_w1[N_LAYERS * WSZ * 2];
__device__ unsigned g_w2[N_LAYERS * WSZ * 2];
__device__ unsigned g_whp[(D_MODEL / 2) * VOCAB_P];

// ---------------- helpers ----------------
__device__ __forceinline__ unsigned f2tf(float x) {
    unsigned r;
    asm("cvt.rna.tf32.f32 %0, %1;" : "=r"(r) : "f"(x));
    return r;
}

__device__ __forceinline__ unsigned packh2(float lo, float hi) {
    __half2 t = __floats2half2_rn(lo, hi);
    return *reinterpret_cast<unsigned*>(&t);
}

__device__ __forceinline__ unsigned prmt(unsigned a, unsigned b, unsigned sel) {
    unsigned r;
    asm("prmt.b32 %0, %1, %2, %3;" : "=r"(r) : "r"(a), "r"(b), "r"(sel));
    return r;
}

__device__ __forceinline__ void mma_f16(float* c, const unsigned* a, const unsigned* b) {
    asm volatile(
        "mma.sync.aligned.m16n8k16.row.col.f32.f16.f16.f32 "
        "{%0,%1,%2,%3}, {%4,%5,%6,%7}, {%8,%9}, {%0,%1,%2,%3};"
        : "+f"(c[0]), "+f"(c[1]), "+f"(c[2]), "+f"(c[3])
        : "r"(a[0]), "r"(a[1]), "r"(a[2]), "r"(a[3]), "r"(b[0]), "r"(b[1]));
}

__device__ __forceinline__ void cp16(unsigned saddr, const unsigned* gptr) {
    asm volatile("cp.async.cg.shared.global [%0], [%1], 16;"
                 :: "r"(saddr), "l"(gptr) : "memory");
}

// ---------------- weight packing: fp32 [rows][N] -> half2 words [rows/2][N] ----------------
__global__ void pack_kernel(const float* __restrict__ src, unsigned* __restrict__ dst,
                            int rows2, int n4) {
    int i = blockIdx.x * 256 + threadIdx.x;
    if (i < rows2 * n4) {
        int r2 = i / n4, c = i % n4;
        size_t N = (size_t)n4 * 4;
        float4 a = *(const float4*)(src + (size_t)(2 * r2) * N + c * 4);
        float4 b = *(const float4*)(src + (size_t)(2 * r2 + 1) * N + c * 4);
        uint4 u;
        u.x = packh2(a.x, b.x); u.y = packh2(a.y, b.y);
        u.z = packh2(a.z, b.z); u.w = packh2(a.w, b.w);
        ((uint4*)dst)[i] = u;
    }
}

// headed qkv weights: [B=L*H][K][64] -> [B][K/2][64] half2 words
__global__ void pack_headed_kernel(const float* __restrict__ src, unsigned* __restrict__ dst,
                                   int nblocks, int K) {
    int i = blockIdx.x * 256 + threadIdx.x;
    int per = (K / 2) * 16;
    if (i < nblocks * per) {
        int b = i / per, rem = i % per;
        int r2 = rem / 16, c = rem % 16;
        const float* s0 = src + ((size_t)b * K + 2 * r2) * 64 + c * 4;
        float4 a = *(const float4*)(s0);
        float4 bb = *(const float4*)(s0 + 64);
        uint4 u;
        u.x = packh2(a.x, bb.x); u.y = packh2(a.y, bb.y);
        u.z = packh2(a.z, bb.z); u.w = packh2(a.w, bb.w);
        ((uint4*)dst)[i] = u;
    }
}

// LM head: [K][VOCAB] -> [K/2][VOCAB_P] half2 words, zero-padded
__global__ void pad_wh_kernel(const float* __restrict__ Wh, unsigned* __restrict__ WhP) {
    int r2 = blockIdx.y;
    int col = blockIdx.x * 256 + threadIdx.x;
    if (col < VOCAB_P) {
        float lo = 0.f, hi = 0.f;
        if (col < VOCAB) {
            lo = Wh[(size_t)(2 * r2) * VOCAB + col];
            hi = Wh[(size_t)(2 * r2 + 1) * VOCAB + col];
        }
        WhP[(size_t)r2 * VOCAB_P + col] = packh2(lo, hi);
    }
}

// ---------------- embedding ----------------
__global__ void embed_kernel(const int* __restrict__ x, const float* __restrict__ wte,
                             const float* __restrict__ wpe, float* __restrict__ h) {
    int row = blockIdx.x;
    int tok = x[row];
    int s = row & (SEQ - 1);
    const float* te = wte + (size_t)tok * D_MODEL;
    const float* pe = wpe + (size_t)s * D_MODEL;
    float* out = h + (size_t)row * D_MODEL;
    for (int d = threadIdx.x; d < D_MODEL; d += 256)
        out[d] = te[d] + pe[d];
}

// ---------------- LN core ----------------
template <bool DOUBLE>
__device__ __forceinline__
void ln_core(float v0, float v1, float v2,
             const float* __restrict__ w1, const float* __restrict__ b1,
             const float* __restrict__ w2, const float* __restrict__ b2,
             __half* __restrict__ yr, float* red, int tid) {
    red[tid] = v0 + v1 + v2;
    __syncthreads();
    for (int s = 128; s > 0; s >>= 1) { if (tid < s) red[tid] += red[tid + s]; __syncthreads(); }
    float mean = red[0] * (1.0f / D_MODEL);
    __syncthreads();
    float d0 = v0 - mean, d1 = v1 - mean, d2 = v2 - mean;
    red[tid] = d0 * d0 + d1 * d1 + d2 * d2;
    __syncthreads();
    for (int s = 128; s > 0; s >>= 1) { if (tid < s) red[tid] += red[tid + s]; __syncthreads(); }
    float rstd = rsqrtf(red[0] * (1.0f / D_MODEL) + 1e-5f);
    float y0 = d0 * rstd * w1[tid]       + b1[tid];
    float y1 = d1 * rstd * w1[tid + 256] + b1[tid + 256];
    float y2 = d2 * rstd * w1[tid + 512] + b1[tid + 512];

    if (DOUBLE) {
        __syncthreads();
        red[tid] = y0 + y1 + y2;
        __syncthreads();
        for (int s = 128; s > 0; s >>= 1) { if (tid < s) red[tid] += red[tid + s]; __syncthreads(); }
        float mean2 = red[0] * (1.0f / D_MODEL);
        __syncthreads();
        float e0 = y0 - mean2, e1 = y1 - mean2, e2 = y2 - mean2;
        red[tid] = e0 * e0 + e1 * e1 + e2 * e2;
        __syncthreads();
        for (int s = 128; s > 0; s >>= 1) { if (tid < s) red[tid] += red[tid + s]; __syncthreads(); }
        float rstd2 = rsqrtf(red[0] * (1.0f / D_MODEL) + 1e-5f);
        y0 = e0 * rstd2 * w2[tid]       + b2[tid];
        y1 = e1 * rstd2 * w2[tid + 256] + b2[tid + 256];
        y2 = e2 * rstd2 * w2[tid + 512] + b2[tid + 512];
    }
    yr[tid]       = __float2half_rn(y0);
    yr[tid + 256] = __float2half_rn(y1);
    yr[tid + 512] = __float2half_rn(y2);
}

template <bool DOUBLE>
__global__ void ln_kernel(const float* __restrict__ x,
                          const float* __restrict__ w1, const float* __restrict__ b1,
                          const float* __restrict__ w2, const float* __restrict__ b2,
                          __half* __restrict__ y) {
    __shared__ float red[256];
    int row = blockIdx.x, tid = threadIdx.x;
    const float* xr = x + (size_t)row * D_MODEL;
    ln_core<DOUBLE>(xr[tid], xr[tid + 256], xr[tid + 512],
                    w1, b1, w2, b2, y + (size_t)row * D_MODEL, red, tid);
}

// fused split-K reduce + residual + LN
template <bool DOUBLE>
__global__ void lnred_kernel(const float* __restrict__ part, const float* __restrict__ bias,
                             float* __restrict__ h,
                             const float* __restrict__ w1, const float* __restrict__ b1,
                             const float* __restrict__ w2, const float* __restrict__ b2,
                             __half* __restrict__ y) {
    __shared__ float red[256];
    int row = blockIdx.x, tid = threadIdx.x;
    float v[3];
#pragma unroll
    for (int i = 0; i < 3; i++) {
        int c = tid + i * 256;
        size_t idx = (size_t)row * D_MODEL + c;
        v[i] = part[idx] + part[idx + (size_t)ROWS * D_MODEL]
             + part[idx + 2 * (size_t)ROWS * D_MODEL] + bias[c] + h[idx];
        h[idx] = v[i];
    }
    ln_core<DOUBLE>(v[0], v[1], v[2], w1, b1, w2, b2,
                    y + (size_t)row * D_MODEL, red, tid);
}

// ---------------- FP16 tensor-core GEMM body (128x256 tile, BK=64) ----------------
// 8 warps, warp tile 64x64 (4 mi x 8 ni m16n8k16); double-buffered 64-deep k stages.
template <bool GELU, bool RESID, bool HEADED, bool OUTH, bool PARTIAL>
__device__ __forceinline__
void gemm_body(const unsigned* __restrict__ A, const unsigned* __restrict__ B,
               const float* __restrict__ bias, const float* __restrict__ resid,
               void* __restrict__ Cv, int M, int N, int K, int NC,
               int bn, int bm, int kOff, int kLen) {
    extern __shared__ unsigned smu[];
    unsigned* Asf = smu;                  // [2][8 mi][4 ks][32][4]
    unsigned* Bsm = smu + ASF_WORDS;      // [2][32 k2][264]
    int tid = threadIdx.x;
    int lane = tid & 31, warp = tid >> 5;
    int wm = (warp & 1) * 64;
    int wn = (warp >> 1) * 64;
    int lr = lane >> 2;
    int lc = lane & 3;
    int lane_s = lr * 4 + (lc ^ ((lr >> 1) & 3));
    int K2 = K >> 1;

    float acc[4][8][4];
#pragma unroll
    for (int mi = 0; mi < 4; mi++)
#pragma unroll
        for (int ni = 0; ni < 8; ni++)
#pragma unroll
            for (int r = 0; r < 4; r++) acc[mi][ni][r] = 0.f;

    int arow_l = tid >> 1;
    int akw    = (tid & 1) * 16;
    int aksb   = (tid & 1) * 2;
    int ami    = arow_l >> 4;
    int alr    = arow_l & 7;
    int ahi    = (arow_l >> 3) & 1;
    int asw    = (alr >> 1) & 3;
    int bkr    = tid >> 4;
    int bcl    = (tid & 15) * 4;

    const unsigned* aptr = A + (size_t)(bm * 128 + arow_l) * K2 + (kOff >> 1) + akw;
    const unsigned* bptr[4];
    int strideB;
    if (HEADED) {
        strideB = 64;
#pragma unroll
        for (int c = 0; c < 4; c++)
            bptr[c] = B + ((size_t)(bn * 4 + c) * K2 + (kOff >> 1) + bkr) * 64 + bcl;
    } else {
        strideB = N;
#pragma unroll
        for (int c = 0; c < 4; c++)
            bptr[c] = B + (size_t)((kOff >> 1) + bkr) * N + bn * 256 + c * 64 + bcl;
    }
    unsigned bsbase = (unsigned)__cvta_generic_to_shared(Bsm) + (bkr * 264 + bcl) * 4;

    uint4 a0, a1, a2, a3;
    auto loadA = [&](int k0) {
        const unsigned* ap = aptr + (k0 >> 1);
        a0 = *(const uint4*)(ap);
        a1 = *(const uint4*)(ap + 4);
        a2 = *(const uint4*)(ap + 8);
        a3 = *(const uint4*)(ap + 12);
    };
    auto storeA = [&](int buf) {
        unsigned ar[16] = {a0.x, a0.y, a0.z, a0.w, a1.x, a1.y, a1.z, a1.w,
                           a2.x, a2.y, a2.z, a2.w, a3.x, a3.y, a3.z, a3.w};
#pragma unroll
        for (int half = 0; half < 2; half++) {
            int ks = aksb + half;
            unsigned* abase = Asf + (((buf * 8 + ami) * 4 + ks) * 32) * 4;
#pragma unroll
            for (int jj = 0; jj < 8; jj++) {
                int ls   = alr * 4 + ((jj & 3) ^ asw);
                int slot = ahi + 2 * (jj >> 2);
                abase[ls * 4 + slot] = ar[half * 8 + jj];
            }
        }
    };
    auto stageB = [&](int k0, int buf) {
#pragma unroll
        for (int rr = 0; rr < 2; rr++)
#pragma unroll
            for (int c = 0; c < 4; c++)
                cp16(bsbase + (buf * 32 + rr * 16) * 264 * 4 + c * 64 * 4,
                     bptr[c] + (size_t)((k0 >> 1) + rr * 16) * strideB);
        asm volatile("cp.async.commit_group;" ::: "memory");
    };

    stageB(0, 0);
    loadA(0);
    storeA(0);
    asm volatile("cp.async.wait_all;" ::: "memory");
    __syncthreads();

    int cur = 0;
    for (int k0 = 0; k0 < kLen; k0 += 64) {
        bool has_next = (k0 + 64) < kLen;
        if (has_next) {
            stageB(k0 + 64, cur ^ 1);
            loadA(k0 + 64);
        }

#pragma unroll
        for (int ks = 0; ks < 4; ks++) {
            unsigned afr[4][4], bfr[8][2];
#pragma unroll
            for (int mi = 0; mi < 4; mi++) {
                int mig = (warp & 1) * 4 + mi;
                uint4 fa = *(const uint4*)(Asf + (((cur * 8 + mig) * 4 + ks) * 32 + lane_s) * 4);
                afr[mi][0] = fa.x; afr[mi][1] = fa.y;
                afr[mi][2] = fa.z; afr[mi][3] = fa.w;
            }
#pragma unroll
            for (int ni = 0; ni < 8; ni++) {
                int n0 = wn + ni * 8;
                bfr[ni][0] = Bsm[(cur * 32 + ks * 8 + lc) * 264 + n0 + lr];
                bfr[ni][1] = Bsm[(cur * 32 + ks * 8 + lc + 4) * 264 + n0 + lr];
            }
#pragma unroll
            for (int mi = 0; mi < 4; mi++)
#pragma unroll
                for (int ni = 0; ni < 8; ni++)
                    mma_f16(acc[mi][ni], afr[mi], bfr[ni]);
        }

        if (has_next) storeA(cur ^ 1);
        asm volatile("cp.async.wait_all;" ::: "memory");
        __syncthreads();
        cur ^= 1;
    }

    float*    Cf = (float*)Cv;
    __half*   Ch = (__half*)Cv;
#pragma unroll
    for (int mi = 0; mi < 4; mi++) {
        int row0 = bm * 128 + wm + mi * 16 + lr;
#pragma unroll
        for (int ni = 0; ni < 8; ni++) {
            int col = bn * 256 + wn + ni * 8 + lc * 2;
#pragma unroll
            for (int half = 0; half < 2; half++) {
                int row = row0 + half * 8;
                if (OUTH) {
                    float v0 = acc[mi][ni][half * 2 + 0] + bias[col];
                    float v1 = acc[mi][ni][half * 2 + 1] + bias[col + 1];
                    if (GELU) {
                        v0 = 0.5f * v0 * (1.0f + erff(v0 * 0.70710678118654752f));
                        v1 = 0.5f * v1 * (1.0f + erff(v1 * 0.70710678118654752f));
                    }
                    __half2 hv = __floats2half2_rn(v0, v1);
                    *(__half2*)(Ch + (size_t)row * NC + col) = hv;
                } else {
#pragma unroll
                    for (int cc = 0; cc < 2; cc++) {
                        int c = col + cc;
                        if (c < NC) {
                            float val = acc[mi][ni][half * 2 + cc];
                            if (PARTIAL) {
                                Cf[(size_t)row * NC + c] = val;
                            } else {
                                val += bias[c];
                                if (GELU) val = 0.5f * val * (1.0f + erff(val * 0.70710678118654752f));
                                if (RESID) val += resid[(size_t)row * NC + c];
                                Cf[(size_t)row * NC + c] = val;
                            }
                        }
                    }
                }
            }
        }
    }
}

template <bool GELU, bool RESID, bool HEADED, bool OUTH, bool PARTIAL>
__global__ __launch_bounds__(256, 1)
void gemm_kernel(const unsigned* __restrict__ A, const unsigned* __restrict__ B,
                 const float* __restrict__ bias, const float* __restrict__ resid,
                 void* __restrict__ C, int M, int N, int K, int NC, int kLen) {
    void* Cv = C;
    int kOff = 0;
    if (PARTIAL) {
        kOff = blockIdx.z * kLen;
        Cv = (float*)C + (size_t)blockIdx.z * M * NC;
    }
    gemm_body<GELU, RESID, HEADED, OUTH, PARTIAL>(A, B, bias, resid, Cv, M, N, K, NC,
                                                  blockIdx.x, blockIdx.y, kOff, kLen);
}

// Fused Q/K/V projection: fp16 in, fp16 out.
__global__ __launch_bounds__(256, 1)
void qkv_kernel(const unsigned* __restrict__ A,
                const unsigned* __restrict__ Wq, const unsigned* __restrict__ Wk,
                const unsigned* __restrict__ Wv,
                const float* __restrict__ bq, const float* __restrict__ bk,
                const float* __restrict__ bv,
                __half* __restrict__ q, __half* __restrict__ k, __half* __restrict__ v) {
    const unsigned* B  = (blockIdx.z == 0) ? Wq : (blockIdx.z == 1) ? Wk : Wv;
    const float* bias  = (blockIdx.z == 0) ? bq : (blockIdx.z == 1) ? bk : bv;
    __half*      C     = (blockIdx.z == 0) ? q  : (blockIdx.z == 1) ? k  : v;
    gemm_body<false, false, true, true, false>(A, B, bias, nullptr, C,
                                               ROWS, D_MODEL, D_MODEL, D_MODEL,
                                               blockIdx.x, blockIdx.y, 0, D_MODEL);
}

// ---------------- fp16 tensor-core causal attention (128-row Q tiles) ----------------
// Q/K row-major half2 words [row][32w] stride 36; V packed as (k,k+1) pairs
// [key2][64w] stride 72; P fp16 [row][32w] stride 36. All phases conflict-free.
#define QF_WORDS (128 * 36)    // 4608
#define KS_WORDS (64 * 36)     // 2304
#define VP_WORDS (32 * 72)     // 2304
#define PS_WORDS (128 * 36)    // 4608
#define ATT_SMEM ((QF_WORDS + KS_WORDS + VP_WORDS + PS_WORDS) * 4)   // 55296
__global__ __launch_bounds__(256, 2)
void attn_kernel(const __half* __restrict__ q, const __half* __restrict__ k,
                 const __half* __restrict__ v, __half* __restrict__ o) {
    extern __shared__ unsigned smu[];
    unsigned* Qs = smu;
    unsigned* Ks = Qs + QF_WORDS;
    unsigned* Vp = Ks + KS_WORDS;
    unsigned* Ps = Vp + VP_WORDS;
    int qi = blockIdx.x, hh = blockIdx.y, b = blockIdx.z;
    int tid = threadIdx.x, lane = tid & 31, warp = tid >> 5;
    int lr = lane >> 2, lc = lane & 3;
    const size_t base = ((size_t)b * SEQ) * D_MODEL + (size_t)hh * HEAD_DIM;
    const float inv_scale = 0.03608439182435161f;   // 1/sqrt(768)

    // stage Q tile: 128 rows x 32 words, row-major (natural fragment words)
#pragma unroll
    for (int i = 0; i < 4; i++) {
        int id = tid + 256 * i;
        int r = id >> 3, c4 = id & 7;
        uint4 qv = *(const uint4*)(q + base + (size_t)(qi * 128 + r) * D_MODEL + c4 * 8);
        *(uint4*)&Qs[r * 36 + c4 * 4] = qv;
    }

    // prefetch K/V tile j=0
    int krow = tid >> 2, kc4 = (tid & 3) * 2;          // K: row, 2 uint4 chunks
    int vp  = tid >> 3, vd0 = (tid & 7) * 8;           // V: pair index, dim base
    uint4 kr0, kr1, vr0, vr1;
    kr0 = *(const uint4*)(k + base + (size_t)krow * D_MODEL + kc4 * 8);
    kr1 = *(const uint4*)(k + base + (size_t)krow * D_MODEL + (kc4 + 1) * 8);
    vr0 = *(const uint4*)(v + base + (size_t)(2 * vp) * D_MODEL + vd0);
    vr1 = *(const uint4*)(v + base + (size_t)(2 * vp + 1) * D_MODEL + vd0);

    float m_[2], l_[2], oacc[8][4];
    m_[0] = m_[1] = -1e30f; l_[0] = l_[1] = 0.f;
#pragma unroll
    for (int ni = 0; ni < 8; ni++)
#pragma unroll
        for (int r = 0; r < 4; r++) oacc[ni][r] = 0.f;

    const unsigned* Qrow0 = Qs + (warp * 16 + lr) * 36;
    const unsigned* Qrow1 = Qrow0 + 8 * 36;
    unsigned* Prow0 = Ps + (warp * 16 + lr) * 36;
    unsigned* Prow1 = Prow0 + 8 * 36;

    int jmax = 2 * qi + 1;
    for (int j = 0; j <= jmax; j++) {
        __syncthreads();
        // stage K (row-major) and V (pair-packed via prmt)
        *(uint4*)&Ks[krow * 36 + kc4 * 4]       = kr0;
        *(uint4*)&Ks[krow * 36 + (kc4 + 1) * 4] = kr1;
        {
            const unsigned* aw = (const unsigned*)&vr0;
            const unsigned* bw = (const unsigned*)&vr1;
            uint4 p0, p1;
            p0.x = prmt(aw[0], bw[0], 0x5410); p0.y = prmt(aw[0], bw[0], 0x7632);
            p0.z = prmt(aw[1], bw[1], 0x5410); p0.w = prmt(aw[1], bw[1], 0x7632);
            p1.x = prmt(aw[2], bw[2], 0x5410); p1.y = prmt(aw[2], bw[2], 0x7632);
            p1.z = prmt(aw[3], bw[3], 0x5410); p1.w = prmt(aw[3], bw[3], 0x7632);
            *(uint4*)&Vp[vp * 72 + vd0]     = p0;
            *(uint4*)&Vp[vp * 72 + vd0 + 4] = p1;
        }
        if (j < jmax) {
            size_t kb = base + (size_t)((j + 1) * 64 + krow) * D_MODEL;
            kr0 = *(const uint4*)(k + kb + kc4 * 8);
            kr1 = *(const uint4*)(k + kb + (kc4 + 1) * 8);
            size_t vb = base + (size_t)((j + 1) * 64 + 2 * vp) * D_MODEL + vd0;
            vr0 = *(const uint4*)(v + vb);
            vr1 = *(const uint4*)(v + vb + D_MODEL);
        }
        __syncthreads();

        // ---- S = Q K^T (fp16 m16n8k16, 4 k-steps) ----
        float s[8][4];
#pragma unroll
        for (int ni = 0; ni < 8; ni++)
#pragma unroll
            for (int r = 0; r < 4; r++) s[ni][r] = 0.f;

#pragma unroll
        for (int ks = 0; ks < 4; ks++) {
            int w0 = ks * 8 + lc;
            unsigned a[4];
            a[0] = Qrow0[w0];
            a[1] = Qrow1[w0];
            a[2] = Qrow0[w0 + 4];
            a[3] = Qrow1[w0 + 4];
#pragma unroll
            for (int ni = 0; ni < 8; ni++) {
                const unsigned* Krow = Ks + (ni * 8 + lr) * 36;
                unsigned bfr[2] = {Krow[w0], Krow[w0 + 4]};
                mma_f16(s[ni], a, bfr);
            }
        }

        // ---- scale + mask + online softmax (unchanged) ----
#pragma unroll
        for (int half = 0; half < 2; half++) {
            int qr = qi * 128 + warp * 16 + lr + half * 8;
            float rm = -1e30f;
#pragma unroll
            for (int ni = 0; ni < 8; ni++)
#pragma unroll
                for (int cc = 0; cc < 2; cc++) {
                    float val = s[ni][half * 2 + cc] * inv_scale;
                    int col = j * 64 + ni * 8 + lc * 2 + cc;
                    if (col > qr) val = -1e30f;
                    s[ni][half * 2 + cc] = val;
                    rm = fmaxf(rm, val);
                }
            rm = fmaxf(rm, __shfl_xor_sync(0xffffffffu, rm, 1));
            rm = fmaxf(rm, __shfl_xor_sync(0xffffffffu, rm, 2));
            float mnew = fmaxf(m_[half], rm);
            float alpha = __expf(m_[half] - mnew);
            float psum = 0.f;
#pragma unroll
            for (int ni = 0; ni < 8; ni++)
#pragma unroll
                for (int cc = 0; cc < 2; cc++) {
                    float p = __expf(s[ni][half * 2 + cc] - mnew);
                    s[ni][half * 2 + cc] = p;
                    psum += p;
                }
            psum += __shfl_xor_sync(0xffffffffu, psum, 1);
            psum += __shfl_xor_sync(0xffffffffu, psum, 2);
            l_[half] = l_[half] * alpha + psum;
            m_[half] = mnew;
#pragma unroll
            for (int ni = 0; ni < 8; ni++) {
                oacc[ni][half * 2 + 0] *= alpha;
                oacc[ni][half * 2 + 1] *= alpha;
            }
        }

        // ---- store P fp16 (half2 pair per word), warp-local ----
#pragma unroll
        for (int ni = 0; ni < 8; ni++) {
            Prow0[ni * 4 + lc] = packh2(s[ni][0], s[ni][1]);
            Prow1[ni * 4 + lc] = packh2(s[ni][2], s[ni][3]);
        }
        __syncwarp();

        // ---- O += P V (fp16 m16n8k16, 4 k-steps over keys) ----
#pragma unroll
        for (int ks = 0; ks < 4; ks++) {
            int w0 = ks * 8 + lc;
            unsigned a[4];
            a[0] = Prow0[w0];
            a[1] = Prow1[w0];
            a[2] = Prow0[w0 + 4];
            a[3] = Prow1[w0 + 4];
#pragma unroll
            for (int ni = 0; ni < 8; ni++) {
                unsigned bfr[2];
                bfr[0] = Vp[(ks * 8 + lc) * 72 + ni * 8 + lr];
                bfr[1] = Vp[(ks * 8 + lc + 4) * 72 + ni * 8 + lr];
                mma_f16(oacc[ni], a, bfr);
            }
        }
    }

    float inv0 = 1.0f / l_[0], inv1 = 1.0f / l_[1];
    int row0 = qi * 128 + warp * 16 + lr;
#pragma unroll
    for (int ni = 0; ni < 8; ni++) {
        int col = ni * 8 + lc * 2;
        __half2* p0 = (__half2*)(o + base + (size_t)row0 * D_MODEL + col);
        __half2* p1 = (__half2*)(o + base + (size_t)(row0 + 8) * D_MODEL + col);
        *p0 = __floats2half2_rn(oacc[ni][0] * inv0, oacc[ni][1] * inv0);
        *p1 = __floats2half2_rn(oacc[ni][2] * inv1, oacc[ni][3] * inv1);
    }
}

// ---------------- launch ----------------
extern "C" void kernel_launch(void* const* d_in, const int* in_sizes, int n_in,
                              void* d_out, int out_size) {
    const int*   x      = (const int*)  d_in[0];
    const float* wte    = (const float*)d_in[1];
    const float* wpe    = (const float*)d_in[2];
    const float* ln1_w  = (const float*)d_in[3];
    const float* ln1_b  = (const float*)d_in[4];
    const float* Wq     = (const float*)d_in[5];
    const float* bq     = (const float*)d_in[6];
    const float* Wk     = (const float*)d_in[7];
    const float* bk     = (const float*)d_in[8];
    const float* Wv     = (const float*)d_in[9];
    const float* bv     = (const float*)d_in[10];
    const float* Wp     = (const float*)d_in[11];
    const float* bp     = (const float*)d_in[12];
    const float* ln2_w  = (const float*)d_in[13];
    const float* ln2_b  = (const float*)d_in[14];
    const float* lnfc_w = (const float*)d_in[15];
    const float* lnfc_b = (const float*)d_in[16];
    const float* W1     = (const float*)d_in[17];
    const float* b1     = (const float*)d_in[18];
    const float* W2     = (const float*)d_in[19];
    const float* b2     = (const float*)d_in[20];
    const float* lnf_w  = (const float*)d_in[21];
    const float* lnf_b  = (const float*)d_in[22];
    const float* Wh     = (const float*)d_in[23];
    const float* bh     = (const float*)d_in[24];
    float* out = (float*)d_out;

    float *h, *part;
    __half *a, *o, *m, *q, *k, *v;
    unsigned *whp, *wq, *wk, *wv, *wp, *w1, *w2;
    cudaGetSymbolAddress((void**)&h, g_h);
    cudaGetSymbolAddress((void**)&a, g_a);
    cudaGetSymbolAddress((void**)&q, g_q);
    cudaGetSymbolAddress((void**)&k, g_k);
    cudaGetSymbolAddress((void**)&v, g_v);
    cudaGetSymbolAddress((void**)&o, g_o);
    cudaGetSymbolAddress((void**)&m, g_m);
    cudaGetSymbolAddress((void**)&part, g_part);
    cudaGetSymbolAddress((void**)&whp, g_whp);
    cudaGetSymbolAddress((void**)&wq, g_wq);
    cudaGetSymbolAddress((void**)&wk, g_wk);
    cudaGetSymbolAddress((void**)&wv, g_wv);
    cudaGetSymbolAddress((void**)&wp, g_wp);
    cudaGetSymbolAddress((void**)&w1, g_w1);
    cudaGetSymbolAddress((void**)&w2, g_w2);

    cudaFuncSetAttribute(attn_kernel, cudaFuncAttributeMaxDynamicSharedMemorySize, ATT_SMEM);
    cudaFuncSetAttribute(qkv_kernel, cudaFuncAttributeMaxDynamicSharedMemorySize, GEMM_SMEM);
    cudaFuncSetAttribute(gemm_kernel<true, false, false, true, false>,
                         cudaFuncAttributeMaxDynamicSharedMemorySize, GEMM_SMEM);   // FF1
    cudaFuncSetAttribute(gemm_kernel<false, false, false, false, false>,
                         cudaFuncAttributeMaxDynamicSharedMemorySize, GEMM_SMEM);   // head
    cudaFuncSetAttribute(gemm_kernel<false, false, false, false, true>,
                         cudaFuncAttributeMaxDynamicSharedMemorySize, GEMM_SMEM);   // split-K

    // one-time weight packing (fp32 -> half2 along K)
    {
        int nH = N_LAYERS * N_HEADS * (D_MODEL / 2) * 16;
        pack_headed_kernel<<<(nH + 255) / 256, 256>>>(Wq, wq, N_LAYERS * N_HEADS, D_MODEL);
        pack_headed_kernel<<<(nH + 255) / 256, 256>>>(Wk, wk, N_LAYERS * N_HEADS, D_MODEL);
        pack_headed_kernel<<<(nH + 255) / 256, 256>>>(Wv, wv, N_LAYERS * N_HEADS, D_MODEL);
        int nP = (N_LAYERS * D_MODEL / 2) * (D_MODEL / 4);
        pack_kernel<<<(nP + 255) / 256, 256>>>(Wp, wp, N_LAYERS * D_MODEL / 2, D_MODEL / 4);
        int n1 = (N_LAYERS * D_MODEL / 2) * (D_FF / 4);
        pack_kernel<<<(n1 + 255) / 256, 256>>>(W1, w1, N_LAYERS * D_MODEL / 2, D_FF / 4);
        int n2 = (N_LAYERS * D_FF / 2) * (D_MODEL / 4);
        pack_kernel<<<(n2 + 255) / 256, 256>>>(W2, w2, N_LAYERS * D_FF / 2, D_MODEL / 4);
        pad_wh_kernel<<<dim3((VOCAB_P + 255) / 256, D_MODEL / 2), 256>>>(Wh, whp);
    }

    embed_kernel<<<ROWS, 256>>>(x, wte, wpe, h);

    dim3 gQKV(D_MODEL / 256, ROWS / 128, 3);          // (3, 32, 3)
    dim3 gSplit(D_MODEL / 256, ROWS / 128, 3);        // (3, 32, 3) split-K
    dim3 gFF1(D_FF / 256, ROWS / 128);                // (12, 32)
    dim3 gHead(VOCAB_P / 256, ROWS / 128);            // (197, 32)
    dim3 gAttn(SEQ / 128, N_HEADS, BATCH);            // (8, 12, 4)

    // layer 0 ln1
    ln_kernel<false><<<ROWS, 256>>>(h, ln1_w, ln1_b, nullptr, nullptr, a);

    const unsigned* aU = (const unsigned*)a;
    const unsigned* oU = (const unsigned*)o;
    const unsigned* mU = (const unsigned*)m;

    for (int l = 0; l < N_LAYERS; l++) {
        const unsigned* wq_l = wq + (size_t)l * WSZ / 2;
        const unsigned* wk_l = wk + (size_t)l * WSZ / 2;
        const unsigned* wv_l = wv + (size_t)l * WSZ / 2;
        const unsigned* wp_l = wp + (size_t)l * WSZ / 2;
        const unsigned* w1_l = w1 + (size_t)l * WSZ * 2;
        const unsigned* w2_l = w2 + (size_t)l * WSZ * 2;

        qkv_kernel<<<gQKV, 256, GEMM_SMEM>>>(aU, wq_l, wk_l, wv_l,
                                             bq + l * D_MODEL, bk + l * D_MODEL, bv + l * D_MODEL,
                                             q, k, v);

        attn_kernel<<<gAttn, 256, ATT_SMEM>>>(q, k, v, o);

        // proj: split-K x3 (K=768 -> 256 each), fused reduce + ln2∘lnfc
        gemm_kernel<false, false, false, false, true><<<gSplit, 256, GEMM_SMEM>>>(
            oU, wp_l, nullptr, nullptr, part, ROWS, D_MODEL, D_MODEL, D_MODEL, 256);
        lnred_kernel<true><<<ROWS, 256>>>(part, bp + l * D_MODEL, h,
                                          ln2_w + l * D_MODEL, ln2_b + l * D_MODEL,
                                          lnfc_w + l * D_MODEL, lnfc_b + l * D_MODEL, a);

        gemm_kernel<true, false, false, true, false><<<gFF1, 256, GEMM_SMEM>>>(
            aU, w1_l, b1 + l * D_FF, nullptr, m, ROWS, D_FF, D_MODEL, D_FF, D_MODEL);

        // FF2: split-K x3 (K=3072 -> 1024 each), fused reduce + next ln1 (or lnf)
        gemm_kernel<false, false, false, false, true><<<gSplit, 256, GEMM_SMEM>>>(
            mU, w2_l, nullptr, nullptr, part, ROWS, D_MODEL, D_FF, D_MODEL, 1024);
        if (l + 1 < N_LAYERS) {
            lnred_kernel<false><<<ROWS, 256>>>(part, b2 + l * D_MODEL, h,
                                               ln1_w + (l + 1) * D_MODEL,
                                               ln1_b + (l + 1) * D_MODEL,
                                               nullptr, nullptr, a);
        } else {
            lnred_kernel<false><<<ROWS, 256>>>(part, b2 + l * D_MODEL, h,
                                               lnf_w, lnf_b, nullptr, nullptr, a);
        }
    }

    gemm_kernel<false, false, false, false, false><<<gHead, 256, GEMM_SMEM>>>(
        aU, whp, bh, nullptr, out, ROWS, VOCAB_P, D_MODEL, VOCAB, D_MODEL);
}